// round 13
// baseline (speedup 1.0000x reference)
#include <cuda_runtime.h>
#include <cuda_bf16.h>

#define Bb 2
#define Nn 512
#define Ff 128
#define LDA 136          /* elements per bf16 tile row (272B) */
#define LDAB 272
#define ROWU4 17

typedef unsigned int u32;
typedef unsigned long long u64;
typedef __nv_bfloat16 bf16;

// ------------------------- device scratch (no allocs) -------------------------
__device__ float g_A[Bb*Nn*Ff];
__device__ float g_Bm[Bb*Nn*Ff];
__device__ float g_hm[Bb*Nn*Ff];
__device__ bf16  g_w2hi[Ff*Ff];
__device__ bf16  g_w2lo[Ff*Ff];
__device__ bf16  g_c1hi[Ff*Ff];

__device__ __forceinline__ float silu_f(float x) {
    return __fdividef(x, 1.f + __expf(-x));
}
__device__ __forceinline__ u32 pkbf(float a, float b) {
    __nv_bfloat162 t = __floats2bfloat162_rn(a, b);
    return *(u32*)&t;
}
__device__ __forceinline__ u32 cvta_s(const void* p) {
    u32 a; asm("{ .reg .u64 t; cvta.to.shared.u64 t, %1; cvt.u32.u64 %0, t; }" : "=r"(a) : "l"(p));
    return a;
}
__device__ __forceinline__ void ldsm4(u32 &a0, u32 &a1, u32 &a2, u32 &a3, u32 addr) {
    asm volatile("ldmatrix.sync.aligned.m8n8.x4.shared.b16 {%0,%1,%2,%3}, [%4];"
                 : "=r"(a0), "=r"(a1), "=r"(a2), "=r"(a3) : "r"(addr));
}
__device__ __forceinline__ void ldsm4t(u32 &a0, u32 &a1, u32 &a2, u32 &a3, u32 addr) {
    asm volatile("ldmatrix.sync.aligned.m8n8.x4.trans.shared.b16 {%0,%1,%2,%3}, [%4];"
                 : "=r"(a0), "=r"(a1), "=r"(a2), "=r"(a3) : "r"(addr));
}
__device__ __forceinline__ void mma16816(float* c, const u32* a, const u32* b) {
    asm volatile("mma.sync.aligned.m16n8k16.row.col.f32.bf16.bf16.f32 "
                 "{%0,%1,%2,%3}, {%4,%5,%6,%7}, {%8,%9}, {%0,%1,%2,%3};"
                 : "+f"(c[0]), "+f"(c[1]), "+f"(c[2]), "+f"(c[3])
                 : "r"(a[0]), "r"(a[1]), "r"(a[2]), "r"(a[3]), "r"(b[0]), "r"(b[1]));
}
#define GBAR(id) asm volatile("bar.sync %0, 128;" :: "r"(id) : "memory")

// ------------------------- SMEM layout (bytes) -------------------------
#define SM_M1HI 0                            /* 128*272 = 34816 */
#define SM_M1LO (SM_M1HI + 34816)
#define SM_MBUF (SM_M1LO + 34816)
#define SM_W2HI (SM_MBUF + 34816)
#define SM_W2LO (SM_W2HI + 34816)
#define SM_C1HI (SM_W2LO + 34816)
#define SM_BMS  (SM_C1HI + 34816)            /* 8*129*4 = 4128 */
#define SM_W1C  (SM_BMS + 4128)
#define SM_B2S  (SM_W1C + 512)
#define SM_CB1S (SM_B2S + 512)
#define SM_CW2S (SM_CB1S + 512)
#define SM_M2D  (SM_CW2S + 512)              /* double-buffered 2*128*4 */
#define SM_EMBP (SM_M2D + 1024)              /* 4*128*4 = 2048 */
#define SM_CI   (SM_EMBP + 2048)
#define SM_MI   (SM_CI + 96)
#define SM_TOTAL (SM_MI + 32 + 16)

/* tail aliases (reuse dead m1hi/m1lo/mbuf regions) */
#define SM_AGGS SM_M1HI                      /* 8*128*4 = 4096 */
#define SM_TRSS (SM_M1HI + 4096)             /* 16*6*4  = 384  */
#define SM_RED  (SM_M1HI + 4608)             /* 512*4   = 2048 */
#define SM_NIN  SM_M1LO                      /* 8*256*4 = 8192 */
#define SM_T1S  SM_MBUF                      /* 8*128*4 = 4096 */

// ---------------------------------------------------------------------------
// k_prep: 4 nodes/block, 512 threads; fused weight hi/lo split; grid = 256
// ---------------------------------------------------------------------------
__global__ __launch_bounds__(512) void k_prep(
    const float* __restrict__ h, const float* __restrict__ mask,
    const float* __restrict__ ew1, const float* __restrict__ eb1,
    const float* __restrict__ ew2, const float* __restrict__ cw1)
{
    __shared__ float hr[4][Ff];
    const int t  = threadIdx.x;
    const int r0 = blockIdx.x * 4;
    const int nd = t >> 7, f = t & 127;
    {
        float hv = h[(r0+nd)*Ff + f] * mask[r0+nd];
        hr[nd][f] = hv;
        g_hm[(r0+nd)*Ff + f] = hv;
    }
    // fused weight split (independent work, no sync needed)
    {
        int widx = blockIdx.x*512 + t;
        if (widx < 2*Ff*Ff) {
            int mat = widx >> 14, rem = widx & 16383;
            if (mat == 0) {
                float v = ew2[rem];
                bf16 hi = __float2bfloat16_rn(v);
                g_w2hi[rem] = hi;
                g_w2lo[rem] = __float2bfloat16_rn(v - __bfloat162float(hi));
            } else {
                g_c1hi[rem] = __float2bfloat16_rn(cw1[rem]);
            }
        }
    }
    __syncthreads();
    float a0 = 0.f, a1 = 0.f;
    float b0 = eb1[f], b1 = 0.f;
    #pragma unroll 8
    for (int k = 0; k < Ff; k += 2) {
        float h0 = hr[nd][k], h1 = hr[nd][k+1];
        a0 += h0 * ew1[k*Ff + f];
        a1 += h1 * ew1[(k+1)*Ff + f];
        b0 += h0 * ew1[(Ff + k)*Ff + f];
        b1 += h1 * ew1[(Ff + k + 1)*Ff + f];
    }
    g_A[(r0+nd)*Ff + f]  = a0 + a1;
    g_Bm[(r0+nd)*Ff + f] = b0 + b1;
}

// ---------------------------------------------------------------------------
// k_edge: 128 blocks, 512 threads; 4 row-groups; build(t+1) overlapped into
// GEMM3(t); warp-local trans; fused node-MLP + coord finalize tail.
// ---------------------------------------------------------------------------
__global__ __launch_bounds__(512, 1) void k_edge(
    const float* __restrict__ coord, const float* __restrict__ mask,
    const float* __restrict__ ew1,   const float* __restrict__ eb2,
    const float* __restrict__ cb1,   const float* __restrict__ cw2,
    const float* __restrict__ nw1,   const float* __restrict__ nb1,
    const float* __restrict__ nw2,   const float* __restrict__ nb2,
    float* __restrict__ out)
{
    extern __shared__ char smc[];
    bf16*  m1hi = (bf16*)(smc + SM_M1HI);
    bf16*  m1lo = (bf16*)(smc + SM_M1LO);
    bf16*  mbuf = (bf16*)(smc + SM_MBUF);
    float* Bms  = (float*)(smc + SM_BMS);
    float* w1c  = (float*)(smc + SM_W1C);
    float* b2s  = (float*)(smc + SM_B2S);
    float* cb1s = (float*)(smc + SM_CB1S);
    float* cw2s = (float*)(smc + SM_CW2S);
    float* m2d  = (float*)(smc + SM_M2D);    /* [2][128] */
    float* embP = (float*)(smc + SM_EMBP);
    float* ci   = (float*)(smc + SM_CI);
    float* mi   = (float*)(smc + SM_MI);

    const int tid = threadIdx.x;
    const int l   = tid & 31;
    const int wr  = tid >> 7;            // row-group 0..3
    const int wc  = (tid >> 5) & 3;      // column warp within group
    const int lt  = tid & 127;
    const int r0  = wr * 32, c0 = wc * 32;
    const int g   = l >> 2, tg = l & 3;
    const int b   = blockIdx.x >> 6;
    const int i0  = (blockIdx.x & 63) * 8;
    const int barid = wr + 1;

    // --- prologue: stage weights + per-block constants ---
    {
        uint4* s1 = (uint4*)(smc + SM_W2HI);
        uint4* s2 = (uint4*)(smc + SM_W2LO);
        uint4* s3 = (uint4*)(smc + SM_C1HI);
        const uint4* d1 = (const uint4*)g_w2hi;
        const uint4* d2 = (const uint4*)g_w2lo;
        const uint4* d3 = (const uint4*)g_c1hi;
        for (int idx = tid; idx < 128*16; idx += 512) {
            int k = idx >> 4, u = idx & 15;
            s1[k*ROWU4 + u] = d1[idx];
            s2[k*ROWU4 + u] = d2[idx];
            s3[k*ROWU4 + u] = d3[idx];
        }
    }
    if (tid < Ff) {
        w1c[tid]  = ew1[2*Ff*Ff + tid];
        b2s[tid]  = eb2[tid];
        cb1s[tid] = cb1[tid];
        cw2s[tid] = cw2[tid];
    }
    if (tid < 8) {
        float mk = mask[b*Nn + i0 + tid];
        mi[tid] = mk;
        ci[tid*3+0] = coord[(b*Nn+i0+tid)*3+0]*mk;
        ci[tid*3+1] = coord[(b*Nn+i0+tid)*3+1]*mk;
        ci[tid*3+2] = coord[(b*Nn+i0+tid)*3+2]*mk;
    }
    for (int idx = tid; idx < 8*Ff; idx += 512) {
        int ii = idx >> 7, f = idx & 127;
        Bms[ii*129 + f] = g_Bm[(b*Nn + i0 + ii)*Ff + f];
    }
    __syncthreads();

    // --- per-thread hoisted epilogue constants ---
    float b2v[4][2], cb1v[4][2], cw2v[4][2];
    #pragma unroll
    for (int nt = 0; nt < 4; nt++) {
        int col = c0 + 8*nt + 2*tg;
        b2v[nt][0]  = b2s[col];    b2v[nt][1]  = b2s[col+1];
        cb1v[nt][0] = cb1s[col];   cb1v[nt][1] = cb1s[col+1];
        cw2v[nt][0] = cw2s[col];   cw2v[nt][1] = cw2s[col+1];
    }

    const u32 m1hi_s = cvta_s(m1hi);
    const u32 m1lo_s = cvta_s(m1lo);
    const u32 mbuf_s = cvta_s(mbuf);
    const u32 w2hi_s = cvta_s(smc + SM_W2HI);
    const u32 w2lo_s = cvta_s(smc + SM_W2LO);
    const u32 c1hi_s = cvta_s(smc + SM_C1HI);
    u32 aoffA[2];
    #pragma unroll
    for (int fr = 0; fr < 2; fr++)
        aoffA[fr] = (u32)((r0 + 16*fr + (l & 15))*LDAB + (l >> 4)*16);
    u32 boffB[2];
    #pragma unroll
    for (int ng = 0; ng < 2; ng++)
        boffB[ng] = (u32)((l & 15)*LDAB + (c0 + 16*ng)*2 + (l >> 4)*16);

    // build-phase constants (this thread's edge row + k-slice)
    const int be  = r0 + (lt >> 2);
    const int bk0 = (lt & 3) * 32;
    const int bii = be >> 4, bjj = be & 15;
    const float* Bmn  = Bms + bii*129 + bk0;
    const float* w1cn = w1c + bk0;
    const float cix = ci[bii*3+0], ciy = ci[bii*3+1], ciz = ci[bii*3+2];
    const float miv = mi[bii];

    // warp-local trans lanes (valid when l < 6)
    const int w_il = l / 3, w_d = l - w_il*3;
    float trs_reg = 0.f;

    float aggp[2][4][2];
    #pragma unroll
    for (int fr = 0; fr < 2; fr++)
        #pragma unroll
        for (int nt = 0; nt < 4; nt++) { aggp[fr][nt][0] = 0.f; aggp[fr][nt][1] = 0.f; }

    // ---- prologue: build tile 0 fully ----
    {
        const int jn = b*Nn + bjj;
        const float mkj = mask[jn];
        float m2 = miv*mkj;
        float dx = cix - coord[jn*3+0]*mkj;
        float dy = ciy - coord[jn*3+1]*mkj;
        float dz = ciz - coord[jn*3+2]*mkj;
        float rv = (dx*dx + dy*dy + dz*dz)*m2;
        if ((lt & 3) == 0) m2d[be] = m2;
        const float* gAn = g_A + jn*Ff + bk0;
        #pragma unroll
        for (int c = 0; c < 8; c++) {
            float4 av = *(const float4*)(gAn + c*4);
            float x0 = silu_f(av.x + Bmn[c*4+0] + rv*w1cn[c*4+0]);
            float x1 = silu_f(av.y + Bmn[c*4+1] + rv*w1cn[c*4+1]);
            float x2 = silu_f(av.z + Bmn[c*4+2] + rv*w1cn[c*4+2]);
            float x3 = silu_f(av.w + Bmn[c*4+3] + rv*w1cn[c*4+3]);
            bf16 h0 = __float2bfloat16_rn(x0), h1 = __float2bfloat16_rn(x1);
            bf16 h2 = __float2bfloat16_rn(x2), h3 = __float2bfloat16_rn(x3);
            uint2 vh, vl;
            vh.x = (*(unsigned short*)&h0) | ((u32)(*(unsigned short*)&h1) << 16);
            vh.y = (*(unsigned short*)&h2) | ((u32)(*(unsigned short*)&h3) << 16);
            vl.x = pkbf(x0-__bfloat162float(h0), x1-__bfloat162float(h1));
            vl.y = pkbf(x2-__bfloat162float(h2), x3-__bfloat162float(h3));
            int eo = be*LDA + bk0 + c*4;
            *(uint2*)(m1hi + eo) = vh;
            *(uint2*)(m1lo + eo) = vl;
        }
    }
    __syncthreads();

    for (int jt = 0; jt < Nn/16; jt++) {
        // ---- GEMM2: acc = m1 @ W2 (3-term hi/lo split) ----
        float acc[2][4][4];
        #pragma unroll
        for (int fr = 0; fr < 2; fr++)
            #pragma unroll
            for (int nt = 0; nt < 4; nt++)
                #pragma unroll
                for (int q = 0; q < 4; q++) acc[fr][nt][q] = 0.f;
        #pragma unroll
        for (int k0 = 0; k0 < 8; k0++) {
            u32 ah[2][4], al[2][4], bh[4][2], bl[4][2];
            #pragma unroll
            for (int fr = 0; fr < 2; fr++) {
                ldsm4(ah[fr][0], ah[fr][1], ah[fr][2], ah[fr][3], m1hi_s + aoffA[fr] + k0*32);
                ldsm4(al[fr][0], al[fr][1], al[fr][2], al[fr][3], m1lo_s + aoffA[fr] + k0*32);
            }
            #pragma unroll
            for (int ng = 0; ng < 2; ng++) {
                ldsm4t(bh[2*ng][0], bh[2*ng][1], bh[2*ng+1][0], bh[2*ng+1][1],
                       w2hi_s + boffB[ng] + k0*16*LDAB);
                ldsm4t(bl[2*ng][0], bl[2*ng][1], bl[2*ng+1][0], bl[2*ng+1][1],
                       w2lo_s + boffB[ng] + k0*16*LDAB);
            }
            #pragma unroll
            for (int fr = 0; fr < 2; fr++)
                #pragma unroll
                for (int nt = 0; nt < 4; nt++) {
                    mma16816(acc[fr][nt], ah[fr], bh[nt]);
                    mma16816(acc[fr][nt], ah[fr], bl[nt]);
                    mma16816(acc[fr][nt], al[fr], bh[nt]);
                }
        }

        // ---- prefetch build(t+1) inputs (latency covered by epi2) ----
        const bool do_build = (jt + 1 < Nn/16);
        const int jn1 = b*Nn + (do_build ? (jt+1)*16 : 0) + bjj;
        const float mkj1 = mask[jn1];
        const float cjx1 = coord[jn1*3+0], cjy1 = coord[jn1*3+1], cjz1 = coord[jn1*3+2];
        const float* gA1 = g_A + jn1*Ff + bk0;
        float4 pa[4];
        pa[0] = *(const float4*)(gA1 + 0);
        pa[1] = *(const float4*)(gA1 + 4);
        pa[2] = *(const float4*)(gA1 + 8);
        pa[3] = *(const float4*)(gA1 + 12);

        // ---- epilogue 2 (registers) ----
        const float* m2dc = m2d + (jt & 1)*128;
        #pragma unroll
        for (int fr = 0; fr < 2; fr++) {
            const int rlo = r0 + 16*fr + g;
            const int rhi = rlo + 8;
            const float m2lo = m2dc[rlo];
            const float m2hi = m2dc[rhi];
            #pragma unroll
            for (int nt = 0; nt < 4; nt++) {
                int col = c0 + 8*nt + 2*tg;
                float v0 = silu_f(acc[fr][nt][0] + b2v[nt][0]) * m2lo;
                float v1 = silu_f(acc[fr][nt][1] + b2v[nt][1]) * m2lo;
                float v2 = silu_f(acc[fr][nt][2] + b2v[nt][0]) * m2hi;
                float v3 = silu_f(acc[fr][nt][3] + b2v[nt][1]) * m2hi;
                aggp[fr][nt][0] += v0 + v2;
                aggp[fr][nt][1] += v1 + v3;
                *(u32*)(mbuf + rlo*LDA + col) = pkbf(v0, v1);
                *(u32*)(mbuf + rhi*LDA + col) = pkbf(v2, v3);
            }
        }
        GBAR(barid);   // mbuf ready; m1 dead for this group -> build(t+1) may write

        // ---- build(t+1) setup ----
        float rv1 = 0.f;
        {
            float m2 = miv*mkj1;
            float dx = cix - cjx1*mkj1;
            float dy = ciy - cjy1*mkj1;
            float dz = ciz - cjz1*mkj1;
            rv1 = (dx*dx + dy*dy + dz*dz)*m2;
            if (do_build && (lt & 3) == 0) m2d[((jt+1) & 1)*128 + be] = m2;
        }

        // ---- GEMM3 k-loop with interleaved build(t+1) chunks ----
        float acc3[2][4][4];
        #pragma unroll
        for (int fr = 0; fr < 2; fr++)
            #pragma unroll
            for (int nt = 0; nt < 4; nt++)
                #pragma unroll
                for (int q = 0; q < 4; q++) acc3[fr][nt][q] = 0.f;
        float4 pb[4];
        #pragma unroll
        for (int k0 = 0; k0 < 8; k0++) {
            u32 af[2][4], bc[4][2];
            #pragma unroll
            for (int fr = 0; fr < 2; fr++)
                ldsm4(af[fr][0], af[fr][1], af[fr][2], af[fr][3], mbuf_s + aoffA[fr] + k0*32);
            #pragma unroll
            for (int ng = 0; ng < 2; ng++)
                ldsm4t(bc[2*ng][0], bc[2*ng][1], bc[2*ng+1][0], bc[2*ng+1][1],
                       c1hi_s + boffB[ng] + k0*16*LDAB);
            if (k0 < 4)
                pb[k0] = *(const float4*)(gA1 + 16 + k0*4);
            if (do_build) {
                float4 av = (k0 < 4) ? pa[k0] : pb[k0-4];
                float x0 = silu_f(av.x + Bmn[k0*4+0] + rv1*w1cn[k0*4+0]);
                float x1 = silu_f(av.y + Bmn[k0*4+1] + rv1*w1cn[k0*4+1]);
                float x2 = silu_f(av.z + Bmn[k0*4+2] + rv1*w1cn[k0*4+2]);
                float x3 = silu_f(av.w + Bmn[k0*4+3] + rv1*w1cn[k0*4+3]);
                bf16 h0 = __float2bfloat16_rn(x0), h1 = __float2bfloat16_rn(x1);
                bf16 h2 = __float2bfloat16_rn(x2), h3 = __float2bfloat16_rn(x3);
                uint2 vh, vl;
                vh.x = (*(unsigned short*)&h0) | ((u32)(*(unsigned short*)&h1) << 16);
                vh.y = (*(unsigned short*)&h2) | ((u32)(*(unsigned short*)&h3) << 16);
                vl.x = pkbf(x0-__bfloat162float(h0), x1-__bfloat162float(h1));
                vl.y = pkbf(x2-__bfloat162float(h2), x3-__bfloat162float(h3));
                int eo = be*LDA + bk0 + k0*4;
                *(uint2*)(m1hi + eo) = vh;
                *(uint2*)(m1lo + eo) = vl;
            }
            #pragma unroll
            for (int fr = 0; fr < 2; fr++)
                #pragma unroll
                for (int nt = 0; nt < 4; nt++)
                    mma16816(acc3[fr][nt], af[fr], bc[nt]);
        }

        // ---- epilogue 3 (registers): embed partials into own embP region ----
        #pragma unroll
        for (int fr = 0; fr < 2; fr++) {
            float plo = 0.f, phi = 0.f;
            #pragma unroll
            for (int nt = 0; nt < 4; nt++) {
                plo += silu_f(acc3[fr][nt][0] + cb1v[nt][0]) * cw2v[nt][0];
                plo += silu_f(acc3[fr][nt][1] + cb1v[nt][1]) * cw2v[nt][1];
                phi += silu_f(acc3[fr][nt][2] + cb1v[nt][0]) * cw2v[nt][0];
                phi += silu_f(acc3[fr][nt][3] + cb1v[nt][1]) * cw2v[nt][1];
            }
            plo += __shfl_xor_sync(0xffffffffu, plo, 1);
            plo += __shfl_xor_sync(0xffffffffu, plo, 2);
            phi += __shfl_xor_sync(0xffffffffu, phi, 1);
            phi += __shfl_xor_sync(0xffffffffu, phi, 2);
            if (tg == 0) {
                embP[wc*128 + r0 + 16*fr + g]     = plo;
                embP[wc*128 + r0 + 16*fr + g + 8] = phi;
            }
        }
        __syncwarp();

        // ---- trans accumulation (warp-local: each warp uses only its embP) ----
        if (l < 6) {
            const int ii = 2*wr + w_il;
            const float cid = ci[ii*3 + w_d];
            const int j0 = jt*16;
            float s = 0.f;
            #pragma unroll
            for (int jj = 0; jj < 16; jj++) {
                int e = ii*16 + jj;
                int jn = b*Nn + j0 + jj;
                float m2 = m2dc[e];
                float cjd = coord[jn*3 + w_d]*mask[jn];
                s += (cid - cjd)*m2*embP[wc*128 + e]*m2;
            }
            trs_reg += s;
        }
        GBAR(barid);   // m1(t+1) fully built for this group
    }
    __syncthreads();   // all groups done; m1/mbuf regions become tail scratch

    // ---- stage agg + trans partials into SMEM ----
    float* aggS = (float*)(smc + SM_AGGS);
    float* trsS = (float*)(smc + SM_TRSS);
    float* red  = (float*)(smc + SM_RED);
    float* nin  = (float*)(smc + SM_NIN);
    float* t1s  = (float*)(smc + SM_T1S);

    #pragma unroll
    for (int fr = 0; fr < 2; fr++) {
        #pragma unroll
        for (int nt = 0; nt < 4; nt++) {
            #pragma unroll
            for (int q = 0; q < 2; q++) {
                float v = aggp[fr][nt][q];
                v += __shfl_xor_sync(0xffffffffu, v, 4);
                v += __shfl_xor_sync(0xffffffffu, v, 8);
                v += __shfl_xor_sync(0xffffffffu, v, 16);
                if (l < 4)
                    aggS[(2*wr + fr)*128 + c0 + 8*nt + 2*tg + q] = v;
            }
        }
    }
    if (l < 6) trsS[(tid >> 5)*6 + l] = trs_reg;
    red[tid] = mask[b*Nn + tid];
    __syncthreads();

    // ---- denom reduction ----
    for (int off = 256; off >= 1; off >>= 1) {
        if (tid < off) red[tid] += red[tid + off];
        __syncthreads();
    }

    // ---- build node-MLP input ----
    for (int idx = tid; idx < 8*256; idx += 512) {
        int ndl = idx >> 8, kk = idx & 255;
        int r = b*Nn + i0 + ndl;
        float mk = mask[r];
        nin[ndl*256 + kk] = (kk < 128 ? g_hm[r*Ff + kk] : aggS[ndl*128 + kk - 128]) * mk;
    }
    __syncthreads();

    // ---- node MLP: thread = (ndl in {0..3} and +4, f); 2 nodes share loads ----
    {
        const int f   = tid & 127;
        const int nd0 = tid >> 7;          // 0..3 -> nodes nd0 and nd0+4
        const float* nA = nin + nd0*256;
        const float* nB = nin + (nd0+4)*256;
        float a0 = nb1[f], a1 = a0;
        #pragma unroll 8
        for (int k = 0; k < 2*Ff; k++) {
            float wv = nw1[k*Ff + f];
            a0 += nA[k]*wv;
            a1 += nB[k]*wv;
        }
        t1s[nd0*128 + f]     = silu_f(a0);
        t1s[(nd0+4)*128 + f] = silu_f(a1);
        __syncthreads();
        const float* tA = t1s + nd0*128;
        const float* tB = t1s + (nd0+4)*128;
        float c2a = nb2[f], c2b = c2a;
        #pragma unroll 8
        for (int k = 0; k < Ff; k++) {
            float wv = nw2[k*Ff + f];
            c2a += tA[k]*wv;
            c2b += tB[k]*wv;
        }
        int rA = b*Nn + i0 + nd0, rB = rA + 4;
        out[rA*Ff + f] = (g_hm[rA*Ff + f] + c2a)*mask[rA];
        out[rB*Ff + f] = (g_hm[rB*Ff + f] + c2b)*mask[rB];
    }

    // ---- coord finalize (24 threads) ----
    if (tid < 24) {
        int ndl = tid/3, d = tid - ndl*3;
        int r = b*Nn + i0 + ndl;
        float mk = mask[r];
        float denom = mk*red[0] + 1e-10f;
        int wrq = ndl >> 1, il = ndl & 1;
        float ts = trsS[(wrq*4+0)*6 + il*3 + d] + trsS[(wrq*4+1)*6 + il*3 + d]
                 + trsS[(wrq*4+2)*6 + il*3 + d] + trsS[(wrq*4+3)*6 + il*3 + d];
        float cm = coord[r*3 + d]*mk;
        out[Bb*Nn*Ff + r*3 + d] = (cm + ts/denom)*mk;
    }
}

// ---------------------------------------------------------------------------
extern "C" void kernel_launch(void* const* d_in, const int* in_sizes, int n_in,
                              void* d_out, int out_size)
{
    const float* h     = (const float*)d_in[0];
    const float* coord = (const float*)d_in[1];
    const float* mask  = (const float*)d_in[2];
    const float* ew1   = (const float*)d_in[3];
    const float* eb1   = (const float*)d_in[4];
    const float* ew2   = (const float*)d_in[5];
    const float* eb2   = (const float*)d_in[6];
    const float* nw1   = (const float*)d_in[7];
    const float* nb1   = (const float*)d_in[8];
    const float* nw2   = (const float*)d_in[9];
    const float* nb2   = (const float*)d_in[10];
    const float* cw1   = (const float*)d_in[11];
    const float* cb1   = (const float*)d_in[12];
    const float* cw2   = (const float*)d_in[13];

    cudaFuncSetAttribute(k_edge, cudaFuncAttributeMaxDynamicSharedMemorySize, SM_TOTAL);

    k_prep<<<Bb*Nn/4, 512>>>(h, mask, ew1, eb1, ew2, cw1);
    k_edge<<<Bb*(Nn/8), 512, SM_TOTAL>>>(coord, mask, ew1, eb2, cb1, cw2,
                                         nw1, nb1, nw2, nb2, (float*)d_out);
}

// round 14
// speedup vs baseline: 1.0881x; 1.0881x over previous
#include <cuda_runtime.h>
#include <cuda_bf16.h>

#define Bb 2
#define Nn 512
#define Ff 128
#define LDA 136          /* elements per bf16 tile row (272B) */
#define LDAB 272
#define ROWU4 17

typedef unsigned int u32;
typedef unsigned long long u64;
typedef __nv_bfloat16 bf16;

// ------------------------- device scratch (no allocs) -------------------------
__device__ float g_A[Bb*Nn*Ff];
__device__ float g_Bm[Bb*Nn*Ff];
__device__ float g_hm[Bb*Nn*Ff];
__device__ float g_agg[Bb*Nn*Ff];
__device__ float g_trans[Bb*Nn*3];
__device__ bf16  g_w2hi[Ff*Ff];
__device__ bf16  g_w2lo[Ff*Ff];
__device__ bf16  g_c1hi[Ff*Ff];

// silu via single-MUFU tanh: silu(x) = 0.5x*(1+tanh(0.5x))
__device__ __forceinline__ float silu_f(float x) {
    float xh = 0.5f*x, t;
    asm("tanh.approx.f32 %0, %1;" : "=f"(t) : "f"(xh));
    return xh + xh*t;
}
__device__ __forceinline__ u32 pkbf(float a, float b) {
    __nv_bfloat162 t = __floats2bfloat162_rn(a, b);
    return *(u32*)&t;
}
__device__ __forceinline__ u32 cvta_s(const void* p) {
    u32 a; asm("{ .reg .u64 t; cvta.to.shared.u64 t, %1; cvt.u32.u64 %0, t; }" : "=r"(a) : "l"(p));
    return a;
}
__device__ __forceinline__ void ldsm4(u32 &a0, u32 &a1, u32 &a2, u32 &a3, u32 addr) {
    asm volatile("ldmatrix.sync.aligned.m8n8.x4.shared.b16 {%0,%1,%2,%3}, [%4];"
                 : "=r"(a0), "=r"(a1), "=r"(a2), "=r"(a3) : "r"(addr));
}
__device__ __forceinline__ void ldsm4t(u32 &a0, u32 &a1, u32 &a2, u32 &a3, u32 addr) {
    asm volatile("ldmatrix.sync.aligned.m8n8.x4.trans.shared.b16 {%0,%1,%2,%3}, [%4];"
                 : "=r"(a0), "=r"(a1), "=r"(a2), "=r"(a3) : "r"(addr));
}
__device__ __forceinline__ void mma16816(float* c, const u32* a, const u32* b) {
    asm volatile("mma.sync.aligned.m16n8k16.row.col.f32.bf16.bf16.f32 "
                 "{%0,%1,%2,%3}, {%4,%5,%6,%7}, {%8,%9}, {%0,%1,%2,%3};"
                 : "+f"(c[0]), "+f"(c[1]), "+f"(c[2]), "+f"(c[3])
                 : "r"(a[0]), "r"(a[1]), "r"(a[2]), "r"(a[3]), "r"(b[0]), "r"(b[1]));
}
#define GBAR(id) asm volatile("bar.sync %0, 128;" :: "r"(id) : "memory")

// ------------------------- SMEM layout (bytes) -------------------------
#define SM_M1HI 0                            /* 128*272 = 34816 */
#define SM_M1LO (SM_M1HI + 34816)
#define SM_MBUF (SM_M1LO + 34816)
#define SM_W2HI (SM_MBUF + 34816)
#define SM_W2LO (SM_W2HI + 34816)
#define SM_C1HI (SM_W2LO + 34816)
#define SM_BMS  (SM_C1HI + 34816)            /* 8*129*4 = 4128 */
#define SM_W1C  (SM_BMS + 4128)
#define SM_B2S  (SM_W1C + 512)
#define SM_CB1S (SM_B2S + 512)
#define SM_CW2S (SM_CB1S + 512)
#define SM_M2D  (SM_CW2S + 512)              /* double-buffered 2*128*4 */
#define SM_EMBP (SM_M2D + 1024)              /* 4*128*4 = 2048 */
#define SM_CI   (SM_EMBP + 2048)
#define SM_MI   (SM_CI + 96)
#define SM_TOTAL (SM_MI + 32 + 16)

// ---------------------------------------------------------------------------
// k_prep: 4 nodes/block, 512 threads; fused weight hi/lo split; grid = 256
// ---------------------------------------------------------------------------
__global__ __launch_bounds__(512) void k_prep(
    const float* __restrict__ h, const float* __restrict__ mask,
    const float* __restrict__ ew1, const float* __restrict__ eb1,
    const float* __restrict__ ew2, const float* __restrict__ cw1)
{
    __shared__ float hr[4][Ff];
    const int t  = threadIdx.x;
    const int r0 = blockIdx.x * 4;
    const int nd = t >> 7, f = t & 127;
    {
        float hv = h[(r0+nd)*Ff + f] * mask[r0+nd];
        hr[nd][f] = hv;
        g_hm[(r0+nd)*Ff + f] = hv;
    }
    // fused weight split (independent work; grid 256*512 = 2*Ff*Ff exactly)
    {
        int widx = blockIdx.x*512 + t;
        int mat = widx >> 14, rem = widx & 16383;
        if (mat == 0) {
            float v = ew2[rem];
            bf16 hi = __float2bfloat16_rn(v);
            g_w2hi[rem] = hi;
            g_w2lo[rem] = __float2bfloat16_rn(v - __bfloat162float(hi));
        } else {
            g_c1hi[rem] = __float2bfloat16_rn(cw1[rem]);
        }
    }
    __syncthreads();
    float a0 = 0.f, a1 = 0.f;
    float b0 = eb1[f], b1 = 0.f;
    #pragma unroll 8
    for (int k = 0; k < Ff; k += 2) {
        float h0 = hr[nd][k], h1 = hr[nd][k+1];
        a0 += h0 * ew1[k*Ff + f];
        a1 += h1 * ew1[(k+1)*Ff + f];
        b0 += h0 * ew1[(Ff + k)*Ff + f];
        b1 += h1 * ew1[(Ff + k + 1)*Ff + f];
    }
    g_A[(r0+nd)*Ff + f]  = a0 + a1;
    g_Bm[(r0+nd)*Ff + f] = b0 + b1;
}

// ---------------------------------------------------------------------------
// k_edge: 128 blocks, 512 threads; 4 row-groups; build(t+1) overlapped
// into GEMM3(t) with register-prefetched A operands. (R12 structure.)
// ---------------------------------------------------------------------------
__global__ __launch_bounds__(512, 1) void k_edge(
    const float* __restrict__ coord, const float* __restrict__ mask,
    const float* __restrict__ ew1,   const float* __restrict__ eb2,
    const float* __restrict__ cb1,   const float* __restrict__ cw2)
{
    extern __shared__ char smc[];
    bf16*  m1hi = (bf16*)(smc + SM_M1HI);
    bf16*  m1lo = (bf16*)(smc + SM_M1LO);
    bf16*  mbuf = (bf16*)(smc + SM_MBUF);
    float* Bms  = (float*)(smc + SM_BMS);
    float* w1c  = (float*)(smc + SM_W1C);
    float* b2s  = (float*)(smc + SM_B2S);
    float* cb1s = (float*)(smc + SM_CB1S);
    float* cw2s = (float*)(smc + SM_CW2S);
    float* m2d  = (float*)(smc + SM_M2D);    /* [2][128] */
    float* embP = (float*)(smc + SM_EMBP);
    float* ci   = (float*)(smc + SM_CI);
    float* mi   = (float*)(smc + SM_MI);

    const int tid = threadIdx.x;
    const int l   = tid & 31;
    const int wr  = tid >> 7;            // row-group 0..3
    const int wc  = (tid >> 5) & 3;      // column warp within group
    const int lt  = tid & 127;
    const int r0  = wr * 32, c0 = wc * 32;
    const int g   = l >> 2, tg = l & 3;
    const int b   = blockIdx.x >> 6;
    const int i0  = (blockIdx.x & 63) * 8;
    const int barid = wr + 1;

    // --- prologue: stage weights + per-block constants ---
    {
        uint4* s1 = (uint4*)(smc + SM_W2HI);
        uint4* s2 = (uint4*)(smc + SM_W2LO);
        uint4* s3 = (uint4*)(smc + SM_C1HI);
        const uint4* d1 = (const uint4*)g_w2hi;
        const uint4* d2 = (const uint4*)g_w2lo;
        const uint4* d3 = (const uint4*)g_c1hi;
        for (int idx = tid; idx < 128*16; idx += 512) {
            int k = idx >> 4, u = idx & 15;
            s1[k*ROWU4 + u] = d1[idx];
            s2[k*ROWU4 + u] = d2[idx];
            s3[k*ROWU4 + u] = d3[idx];
        }
    }
    if (tid < Ff) {
        w1c[tid]  = ew1[2*Ff*Ff + tid];
        b2s[tid]  = eb2[tid];
        cb1s[tid] = cb1[tid];
        cw2s[tid] = cw2[tid];
    }
    if (tid < 8) {
        float mk = mask[b*Nn + i0 + tid];
        mi[tid] = mk;
        ci[tid*3+0] = coord[(b*Nn+i0+tid)*3+0]*mk;
        ci[tid*3+1] = coord[(b*Nn+i0+tid)*3+1]*mk;
        ci[tid*3+2] = coord[(b*Nn+i0+tid)*3+2]*mk;
    }
    for (int idx = tid; idx < 8*Ff; idx += 512) {
        int ii = idx >> 7, f = idx & 127;
        Bms[ii*129 + f] = g_Bm[(b*Nn + i0 + ii)*Ff + f];
    }
    __syncthreads();

    // --- per-thread hoisted epilogue constants ---
    float b2v[4][2], cb1v[4][2], cw2v[4][2];
    #pragma unroll
    for (int nt = 0; nt < 4; nt++) {
        int col = c0 + 8*nt + 2*tg;
        b2v[nt][0]  = b2s[col];    b2v[nt][1]  = b2s[col+1];
        cb1v[nt][0] = cb1s[col];   cb1v[nt][1] = cb1s[col+1];
        cw2v[nt][0] = cw2s[col];   cw2v[nt][1] = cw2s[col+1];
    }

    const u32 m1hi_s = cvta_s(m1hi);
    const u32 m1lo_s = cvta_s(m1lo);
    const u32 mbuf_s = cvta_s(mbuf);
    const u32 w2hi_s = cvta_s(smc + SM_W2HI);
    const u32 w2lo_s = cvta_s(smc + SM_W2LO);
    const u32 c1hi_s = cvta_s(smc + SM_C1HI);
    u32 aoffA[2];
    #pragma unroll
    for (int fr = 0; fr < 2; fr++)
        aoffA[fr] = (u32)((r0 + 16*fr + (l & 15))*LDAB + (l >> 4)*16);
    u32 boffB[2];
    #pragma unroll
    for (int ng = 0; ng < 2; ng++)
        boffB[ng] = (u32)((l & 15)*LDAB + (c0 + 16*ng)*2 + (l >> 4)*16);

    // build-phase constants (this thread's edge row + k-slice)
    const int be  = r0 + (lt >> 2);
    const int bk0 = (lt & 3) * 32;
    const int bii = be >> 4, bjj = be & 15;
    const float* Bmn  = Bms + bii*129 + bk0;
    const float* w1cn = w1c + bk0;
    const float cix = ci[bii*3+0], ciy = ci[bii*3+1], ciz = ci[bii*3+2];
    const float miv = mi[bii];

    const int t_il = lt / 3, t_d = lt - t_il*3;
    float trs_reg = 0.f;

    float aggp[2][4][2];
    #pragma unroll
    for (int fr = 0; fr < 2; fr++)
        #pragma unroll
        for (int nt = 0; nt < 4; nt++) { aggp[fr][nt][0] = 0.f; aggp[fr][nt][1] = 0.f; }

    // ---- prologue: build tile 0 fully ----
    {
        const int jn = b*Nn + bjj;
        const float mkj = mask[jn];
        float m2 = miv*mkj;
        float dx = cix - coord[jn*3+0]*mkj;
        float dy = ciy - coord[jn*3+1]*mkj;
        float dz = ciz - coord[jn*3+2]*mkj;
        float rv = (dx*dx + dy*dy + dz*dz)*m2;
        if ((lt & 3) == 0) m2d[be] = m2;
        const float* gAn = g_A + jn*Ff + bk0;
        #pragma unroll
        for (int c = 0; c < 8; c++) {
            float4 av = *(const float4*)(gAn + c*4);
            float x0 = silu_f(av.x + Bmn[c*4+0] + rv*w1cn[c*4+0]);
            float x1 = silu_f(av.y + Bmn[c*4+1] + rv*w1cn[c*4+1]);
            float x2 = silu_f(av.z + Bmn[c*4+2] + rv*w1cn[c*4+2]);
            float x3 = silu_f(av.w + Bmn[c*4+3] + rv*w1cn[c*4+3]);
            bf16 h0 = __float2bfloat16_rn(x0), h1 = __float2bfloat16_rn(x1);
            bf16 h2 = __float2bfloat16_rn(x2), h3 = __float2bfloat16_rn(x3);
            uint2 vh, vl;
            vh.x = (*(unsigned short*)&h0) | ((u32)(*(unsigned short*)&h1) << 16);
            vh.y = (*(unsigned short*)&h2) | ((u32)(*(unsigned short*)&h3) << 16);
            vl.x = pkbf(x0-__bfloat162float(h0), x1-__bfloat162float(h1));
            vl.y = pkbf(x2-__bfloat162float(h2), x3-__bfloat162float(h3));
            int eo = be*LDA + bk0 + c*4;
            *(uint2*)(m1hi + eo) = vh;
            *(uint2*)(m1lo + eo) = vl;
        }
    }
    __syncthreads();

    for (int jt = 0; jt < Nn/16; jt++) {
        // ---- GEMM2: acc = m1 @ W2 (3-term hi/lo split) ----
        float acc[2][4][4];
        #pragma unroll
        for (int fr = 0; fr < 2; fr++)
            #pragma unroll
            for (int nt = 0; nt < 4; nt++)
                #pragma unroll
                for (int q = 0; q < 4; q++) acc[fr][nt][q] = 0.f;
        #pragma unroll
        for (int k0 = 0; k0 < 8; k0++) {
            u32 ah[2][4], al[2][4], bh[4][2], bl[4][2];
            #pragma unroll
            for (int fr = 0; fr < 2; fr++) {
                ldsm4(ah[fr][0], ah[fr][1], ah[fr][2], ah[fr][3], m1hi_s + aoffA[fr] + k0*32);
                ldsm4(al[fr][0], al[fr][1], al[fr][2], al[fr][3], m1lo_s + aoffA[fr] + k0*32);
            }
            #pragma unroll
            for (int ng = 0; ng < 2; ng++) {
                ldsm4t(bh[2*ng][0], bh[2*ng][1], bh[2*ng+1][0], bh[2*ng+1][1],
                       w2hi_s + boffB[ng] + k0*16*LDAB);
                ldsm4t(bl[2*ng][0], bl[2*ng][1], bl[2*ng+1][0], bl[2*ng+1][1],
                       w2lo_s + boffB[ng] + k0*16*LDAB);
            }
            #pragma unroll
            for (int fr = 0; fr < 2; fr++)
                #pragma unroll
                for (int nt = 0; nt < 4; nt++) {
                    mma16816(acc[fr][nt], ah[fr], bh[nt]);
                    mma16816(acc[fr][nt], ah[fr], bl[nt]);
                    mma16816(acc[fr][nt], al[fr], bh[nt]);
                }
        }

        // ---- prefetch build(t+1) inputs (latency covered by epi2) ----
        const bool do_build = (jt + 1 < Nn/16);
        const int jn1 = b*Nn + (do_build ? (jt+1)*16 : 0) + bjj;
        const float mkj1 = mask[jn1];
        const float cjx1 = coord[jn1*3+0], cjy1 = coord[jn1*3+1], cjz1 = coord[jn1*3+2];
        const float* gA1 = g_A + jn1*Ff + bk0;
        float4 pa[4];
        pa[0] = *(const float4*)(gA1 + 0);
        pa[1] = *(const float4*)(gA1 + 4);
        pa[2] = *(const float4*)(gA1 + 8);
        pa[3] = *(const float4*)(gA1 + 12);

        // ---- epilogue 2 (registers) ----
        const float* m2dc = m2d + (jt & 1)*128;
        #pragma unroll
        for (int fr = 0; fr < 2; fr++) {
            const int rlo = r0 + 16*fr + g;
            const int rhi = rlo + 8;
            const float m2lo = m2dc[rlo];
            const float m2hi = m2dc[rhi];
            #pragma unroll
            for (int nt = 0; nt < 4; nt++) {
                int col = c0 + 8*nt + 2*tg;
                float v0 = silu_f(acc[fr][nt][0] + b2v[nt][0]) * m2lo;
                float v1 = silu_f(acc[fr][nt][1] + b2v[nt][1]) * m2lo;
                float v2 = silu_f(acc[fr][nt][2] + b2v[nt][0]) * m2hi;
                float v3 = silu_f(acc[fr][nt][3] + b2v[nt][1]) * m2hi;
                aggp[fr][nt][0] += v0 + v2;
                aggp[fr][nt][1] += v1 + v3;
                *(u32*)(mbuf + rlo*LDA + col) = pkbf(v0, v1);
                *(u32*)(mbuf + rhi*LDA + col) = pkbf(v2, v3);
            }
        }
        GBAR(barid);   // mbuf ready; m1 dead for this group -> build(t+1) may write

        // ---- build(t+1) setup ----
        float rv1 = 0.f;
        {
            float m2 = miv*mkj1;
            float dx = cix - cjx1*mkj1;
            float dy = ciy - cjy1*mkj1;
            float dz = ciz - cjz1*mkj1;
            rv1 = (dx*dx + dy*dy + dz*dz)*m2;
            if (do_build && (lt & 3) == 0) m2d[((jt+1) & 1)*128 + be] = m2;
        }

        // ---- GEMM3 k-loop with interleaved build(t+1) chunks ----
        float acc3[2][4][4];
        #pragma unroll
        for (int fr = 0; fr < 2; fr++)
            #pragma unroll
            for (int nt = 0; nt < 4; nt++)
                #pragma unroll
                for (int q = 0; q < 4; q++) acc3[fr][nt][q] = 0.f;
        float4 pb[4];
        #pragma unroll
        for (int k0 = 0; k0 < 8; k0++) {
            u32 af[2][4], bc[4][2];
            #pragma unroll
            for (int fr = 0; fr < 2; fr++)
                ldsm4(af[fr][0], af[fr][1], af[fr][2], af[fr][3], mbuf_s + aoffA[fr] + k0*32);
            #pragma unroll
            for (int ng = 0; ng < 2; ng++)
                ldsm4t(bc[2*ng][0], bc[2*ng][1], bc[2*ng+1][0], bc[2*ng+1][1],
                       c1hi_s + boffB[ng] + k0*16*LDAB);
            if (k0 < 4)
                pb[k0] = *(const float4*)(gA1 + 16 + k0*4);
            if (do_build) {
                float4 av = (k0 < 4) ? pa[k0] : pb[k0-4];
                float x0 = silu_f(av.x + Bmn[k0*4+0] + rv1*w1cn[k0*4+0]);
                float x1 = silu_f(av.y + Bmn[k0*4+1] + rv1*w1cn[k0*4+1]);
                float x2 = silu_f(av.z + Bmn[k0*4+2] + rv1*w1cn[k0*4+2]);
                float x3 = silu_f(av.w + Bmn[k0*4+3] + rv1*w1cn[k0*4+3]);
                bf16 h0 = __float2bfloat16_rn(x0), h1 = __float2bfloat16_rn(x1);
                bf16 h2 = __float2bfloat16_rn(x2), h3 = __float2bfloat16_rn(x3);
                uint2 vh, vl;
                vh.x = (*(unsigned short*)&h0) | ((u32)(*(unsigned short*)&h1) << 16);
                vh.y = (*(unsigned short*)&h2) | ((u32)(*(unsigned short*)&h3) << 16);
                vl.x = pkbf(x0-__bfloat162float(h0), x1-__bfloat162float(h1));
                vl.y = pkbf(x2-__bfloat162float(h2), x3-__bfloat162float(h3));
                int eo = be*LDA + bk0 + k0*4;
                *(uint2*)(m1hi + eo) = vh;
                *(uint2*)(m1lo + eo) = vl;
            }
            #pragma unroll
            for (int fr = 0; fr < 2; fr++)
                #pragma unroll
                for (int nt = 0; nt < 4; nt++)
                    mma16816(acc3[fr][nt], af[fr], bc[nt]);
        }

        // ---- epilogue 3 (registers): embed partials ----
        #pragma unroll
        for (int fr = 0; fr < 2; fr++) {
            float plo = 0.f, phi = 0.f;
            #pragma unroll
            for (int nt = 0; nt < 4; nt++) {
                plo += silu_f(acc3[fr][nt][0] + cb1v[nt][0]) * cw2v[nt][0];
                plo += silu_f(acc3[fr][nt][1] + cb1v[nt][1]) * cw2v[nt][1];
                phi += silu_f(acc3[fr][nt][2] + cb1v[nt][0]) * cw2v[nt][0];
                phi += silu_f(acc3[fr][nt][3] + cb1v[nt][1]) * cw2v[nt][1];
            }
            plo += __shfl_xor_sync(0xffffffffu, plo, 1);
            plo += __shfl_xor_sync(0xffffffffu, plo, 2);
            phi += __shfl_xor_sync(0xffffffffu, phi, 1);
            phi += __shfl_xor_sync(0xffffffffu, phi, 2);
            if (tg == 0) {
                embP[wc*128 + r0 + 16*fr + g]     = plo;
                embP[wc*128 + r0 + 16*fr + g + 8] = phi;
            }
        }
        GBAR(barid);   // embP ready; m1(t+1) fully built for this group

        // ---- trans accumulation (6 threads/group, deterministic) ----
        if (lt < 6) {
            const int ii = 2*wr + t_il;
            const float cid = ci[ii*3 + t_d];
            const int j0 = jt*16;
            float s = 0.f;
            #pragma unroll
            for (int jj = 0; jj < 16; jj++) {
                int e = ii*16 + jj;
                int jn = b*Nn + j0 + jj;
                float m2 = m2dc[e];
                float cjd = coord[jn*3 + t_d]*mask[jn];
                float em = embP[e] + embP[128+e] + embP[256+e] + embP[384+e];
                s += (cid - cjd)*m2*em*m2;
            }
            trs_reg += s;
        }
    }

    // ---- final agg reduction ----
    #pragma unroll
    for (int fr = 0; fr < 2; fr++) {
        #pragma unroll
        for (int nt = 0; nt < 4; nt++) {
            #pragma unroll
            for (int q = 0; q < 2; q++) {
                float v = aggp[fr][nt][q];
                v += __shfl_xor_sync(0xffffffffu, v, 4);
                v += __shfl_xor_sync(0xffffffffu, v, 8);
                v += __shfl_xor_sync(0xffffffffu, v, 16);
                if (l < 4)
                    g_agg[(b*Nn + i0 + 2*wr + fr)*Ff + c0 + 8*nt + 2*tg + q] = v;
            }
        }
    }
    if (lt < 6)
        g_trans[(b*Nn + i0 + 2*wr + t_il)*3 + t_d] = trs_reg;
}

// ---------------------------------------------------------------------------
// k_node: 4 nodes/block, 512 threads; dual accumulators for chain ILP
// ---------------------------------------------------------------------------
__global__ __launch_bounds__(512) void k_node(
    const float* __restrict__ coord, const float* __restrict__ mask,
    const float* __restrict__ nw1, const float* __restrict__ nb1,
    const float* __restrict__ nw2, const float* __restrict__ nb2,
    float* __restrict__ out)
{
    __shared__ float nin[4][2*Ff];
    __shared__ float t1s[4][Ff];
    __shared__ float red[512];
    const int t  = threadIdx.x;
    const int r0 = blockIdx.x * 4;
    const int b  = r0 >> 9;
    const int nd = t >> 7, f = t & 127;
    const int r  = r0 + nd;

    {
        float mk = mask[r];
        nin[nd][f]      = g_hm[r*Ff + f] * mk;
        nin[nd][Ff + f] = g_agg[r*Ff + f] * mk;
    }
    red[t] = mask[b*Nn + t];
    __syncthreads();
    for (int off = 256; off >= 1; off >>= 1) {
        if (t < off) red[t] += red[t + off];
        __syncthreads();
    }

    float a0 = nb1[f], a1 = 0.f;
    #pragma unroll 8
    for (int k = 0; k < 2*Ff; k += 2) {
        a0 += nin[nd][k]*nw1[k*Ff + f];
        a1 += nin[nd][k+1]*nw1[(k+1)*Ff + f];
    }
    t1s[nd][f] = silu_f(a0 + a1);
    __syncthreads();
    float c0 = nb2[f], c1 = 0.f;
    #pragma unroll 8
    for (int k = 0; k < Ff; k += 2) {
        c0 += t1s[nd][k]*nw2[k*Ff + f];
        c1 += t1s[nd][k+1]*nw2[(k+1)*Ff + f];
    }
    {
        float mk = mask[r];
        out[r*Ff + f] = (g_hm[r*Ff + f] + c0 + c1)*mk;
    }
    if (t < 12) {
        int nd2 = t/3, d = t - nd2*3;
        int rr = r0 + nd2;
        float mk = mask[rr];
        float denom = mk*red[0] + 1e-10f;
        float cm = coord[rr*3 + d]*mk;
        out[Bb*Nn*Ff + rr*3 + d] = (cm + g_trans[rr*3 + d]/denom)*mk;
    }
}

// ---------------------------------------------------------------------------
extern "C" void kernel_launch(void* const* d_in, const int* in_sizes, int n_in,
                              void* d_out, int out_size)
{
    const float* h     = (const float*)d_in[0];
    const float* coord = (const float*)d_in[1];
    const float* mask  = (const float*)d_in[2];
    const float* ew1   = (const float*)d_in[3];
    const float* eb1   = (const float*)d_in[4];
    const float* ew2   = (const float*)d_in[5];
    const float* eb2   = (const float*)d_in[6];
    const float* nw1   = (const float*)d_in[7];
    const float* nb1   = (const float*)d_in[8];
    const float* nw2   = (const float*)d_in[9];
    const float* nb2   = (const float*)d_in[10];
    const float* cw1   = (const float*)d_in[11];
    const float* cb1   = (const float*)d_in[12];
    const float* cw2   = (const float*)d_in[13];

    cudaFuncSetAttribute(k_edge, cudaFuncAttributeMaxDynamicSharedMemorySize, SM_TOTAL);

    k_prep<<<Bb*Nn/4, 512>>>(h, mask, ew1, eb1, ew2, cw1);
    k_edge<<<Bb*(Nn/8), 512, SM_TOTAL>>>(coord, mask, ew1, eb2, cb1, cw2);
    k_node<<<Bb*Nn/4, 512>>>(coord, mask, nw1, nb1, nw2, nb2, (float*)d_out);
}

// round 15
// speedup vs baseline: 1.1903x; 1.0940x over previous
#include <cuda_runtime.h>
#include <cuda_fp16.h>

#define Bb 2
#define Nn 512
#define Ff 128
#define LDA 136          /* elements per fp16 tile row (272B) */
#define LDAB 272
#define ROWU4 17

typedef unsigned int u32;
typedef unsigned long long u64;

// ------------------------- device scratch (no allocs) -------------------------
__device__ float g_A[Bb*Nn*Ff];
__device__ float g_Bm[Bb*Nn*Ff];
__device__ float g_hm[Bb*Nn*Ff];
__device__ float g_agg[Bb*Nn*Ff];
__device__ float g_trans[Bb*Nn*3];
__device__ __half g_w2h[Ff*Ff];   // W2 fp16, [k][f]
__device__ __half g_c1h[Ff*Ff];   // coord_w1 fp16, [k][f]

// silu via single-MUFU tanh: silu(x) = 0.5x*(1+tanh(0.5x))
__device__ __forceinline__ float silu_f(float x) {
    float xh = 0.5f*x, t;
    asm("tanh.approx.f32 %0, %1;" : "=f"(t) : "f"(xh));
    return xh + xh*t;
}
__device__ __forceinline__ u32 pkh(float a, float b) {
    __half2 t = __floats2half2_rn(a, b);
    return *(u32*)&t;
}
__device__ __forceinline__ u32 cvta_s(const void* p) {
    u32 a; asm("{ .reg .u64 t; cvta.to.shared.u64 t, %1; cvt.u32.u64 %0, t; }" : "=r"(a) : "l"(p));
    return a;
}
__device__ __forceinline__ void ldsm4(u32 &a0, u32 &a1, u32 &a2, u32 &a3, u32 addr) {
    asm volatile("ldmatrix.sync.aligned.m8n8.x4.shared.b16 {%0,%1,%2,%3}, [%4];"
                 : "=r"(a0), "=r"(a1), "=r"(a2), "=r"(a3) : "r"(addr));
}
__device__ __forceinline__ void ldsm4t(u32 &a0, u32 &a1, u32 &a2, u32 &a3, u32 addr) {
    asm volatile("ldmatrix.sync.aligned.m8n8.x4.trans.shared.b16 {%0,%1,%2,%3}, [%4];"
                 : "=r"(a0), "=r"(a1), "=r"(a2), "=r"(a3) : "r"(addr));
}
__device__ __forceinline__ void mma_h(float* c, const u32* a, const u32* b) {
    asm volatile("mma.sync.aligned.m16n8k16.row.col.f32.f16.f16.f32 "
                 "{%0,%1,%2,%3}, {%4,%5,%6,%7}, {%8,%9}, {%0,%1,%2,%3};"
                 : "+f"(c[0]), "+f"(c[1]), "+f"(c[2]), "+f"(c[3])
                 : "r"(a[0]), "r"(a[1]), "r"(a[2]), "r"(a[3]), "r"(b[0]), "r"(b[1]));
}
#define GBAR(id) asm volatile("bar.sync %0, 128;" :: "r"(id) : "memory")

// ------------------------- SMEM layout (bytes) -------------------------
#define SM_M1HI 0                            /* 128*272 = 34816 */
#define SM_M1LO (SM_M1HI + 34816)
#define SM_MBUF (SM_M1LO + 34816)
#define SM_W2H  (SM_MBUF + 34816)
#define SM_C1H  (SM_W2H + 34816)
#define SM_BMS  (SM_C1H + 34816)             /* 8*129*4 = 4128 */
#define SM_W1C  (SM_BMS + 4128)
#define SM_B2S  (SM_W1C + 512)
#define SM_CB1S (SM_B2S + 512)
#define SM_CW2S (SM_CB1S + 512)
#define SM_M2D  (SM_CW2S + 512)              /* double-buffered 2*128*4 */
#define SM_EMBP (SM_M2D + 1024)              /* 4*128*4 = 2048 */
#define SM_CI   (SM_EMBP + 2048)
#define SM_MI   (SM_CI + 96)
#define SM_TOTAL (SM_MI + 32 + 16)

// ---------------------------------------------------------------------------
// k_prep: 4 nodes/block, 512 threads; fused fp16 weight conversion; grid = 256
// ---------------------------------------------------------------------------
__global__ __launch_bounds__(512) void k_prep(
    const float* __restrict__ h, const float* __restrict__ mask,
    const float* __restrict__ ew1, const float* __restrict__ eb1,
    const float* __restrict__ ew2, const float* __restrict__ cw1)
{
    __shared__ float hr[4][Ff];
    const int t  = threadIdx.x;
    const int r0 = blockIdx.x * 4;
    const int nd = t >> 7, f = t & 127;
    {
        float hv = h[(r0+nd)*Ff + f] * mask[r0+nd];
        hr[nd][f] = hv;
        g_hm[(r0+nd)*Ff + f] = hv;
    }
    // fused fp16 weight conversion (independent work)
    {
        int widx = blockIdx.x*512 + t;
        if (widx < 2*Ff*Ff) {
            int mat = widx >> 14, rem = widx & 16383;
            if (mat == 0) g_w2h[rem] = __float2half_rn(ew2[rem]);
            else          g_c1h[rem] = __float2half_rn(cw1[rem]);
        }
    }
    __syncthreads();
    float a0 = 0.f, a1 = 0.f;
    float b0 = eb1[f], b1 = 0.f;
    #pragma unroll 8
    for (int k = 0; k < Ff; k += 2) {
        float h0 = hr[nd][k], h1 = hr[nd][k+1];
        a0 += h0 * ew1[k*Ff + f];
        a1 += h1 * ew1[(k+1)*Ff + f];
        b0 += h0 * ew1[(Ff + k)*Ff + f];
        b1 += h1 * ew1[(Ff + k + 1)*Ff + f];
    }
    g_A[(r0+nd)*Ff + f]  = a0 + a1;
    g_Bm[(r0+nd)*Ff + f] = b0 + b1;
}

// ---------------------------------------------------------------------------
// k_edge: 128 blocks, 512 threads; 4 row-groups; build(t+1) overlapped
// into GEMM3(t); fp16 2-term GEMM2 (A hi/lo split, single fp16 W2).
// ---------------------------------------------------------------------------
__global__ __launch_bounds__(512, 1) void k_edge(
    const float* __restrict__ coord, const float* __restrict__ mask,
    const float* __restrict__ ew1,   const float* __restrict__ eb2,
    const float* __restrict__ cb1,   const float* __restrict__ cw2)
{
    extern __shared__ char smc[];
    __half* m1hi = (__half*)(smc + SM_M1HI);
    __half* m1lo = (__half*)(smc + SM_M1LO);
    __half* mbuf = (__half*)(smc + SM_MBUF);
    float* Bms  = (float*)(smc + SM_BMS);
    float* w1c  = (float*)(smc + SM_W1C);
    float* b2s  = (float*)(smc + SM_B2S);
    float* cb1s = (float*)(smc + SM_CB1S);
    float* cw2s = (float*)(smc + SM_CW2S);
    float* m2d  = (float*)(smc + SM_M2D);    /* [2][128] */
    float* embP = (float*)(smc + SM_EMBP);
    float* ci   = (float*)(smc + SM_CI);
    float* mi   = (float*)(smc + SM_MI);

    const int tid = threadIdx.x;
    const int l   = tid & 31;
    const int wr  = tid >> 7;            // row-group 0..3
    const int wc  = (tid >> 5) & 3;      // column warp within group
    const int lt  = tid & 127;
    const int r0  = wr * 32, c0 = wc * 32;
    const int g   = l >> 2, tg = l & 3;
    const int b   = blockIdx.x >> 6;
    const int i0  = (blockIdx.x & 63) * 8;
    const int barid = wr + 1;

    // --- prologue: stage weights + per-block constants ---
    {
        uint4* s1 = (uint4*)(smc + SM_W2H);
        uint4* s3 = (uint4*)(smc + SM_C1H);
        const uint4* d1 = (const uint4*)g_w2h;
        const uint4* d3 = (const uint4*)g_c1h;
        for (int idx = tid; idx < 128*16; idx += 512) {
            int k = idx >> 4, u = idx & 15;
            s1[k*ROWU4 + u] = d1[idx];
            s3[k*ROWU4 + u] = d3[idx];
        }
    }
    if (tid < Ff) {
        w1c[tid]  = ew1[2*Ff*Ff + tid];
        b2s[tid]  = eb2[tid];
        cb1s[tid] = cb1[tid];
        cw2s[tid] = cw2[tid];
    }
    if (tid < 8) {
        float mk = mask[b*Nn + i0 + tid];
        mi[tid] = mk;
        ci[tid*3+0] = coord[(b*Nn+i0+tid)*3+0]*mk;
        ci[tid*3+1] = coord[(b*Nn+i0+tid)*3+1]*mk;
        ci[tid*3+2] = coord[(b*Nn+i0+tid)*3+2]*mk;
    }
    for (int idx = tid; idx < 8*Ff; idx += 512) {
        int ii = idx >> 7, f = idx & 127;
        Bms[ii*129 + f] = g_Bm[(b*Nn + i0 + ii)*Ff + f];
    }
    __syncthreads();

    // --- per-thread hoisted epilogue constants ---
    float b2v[4][2], cb1v[4][2], cw2v[4][2];
    #pragma unroll
    for (int nt = 0; nt < 4; nt++) {
        int col = c0 + 8*nt + 2*tg;
        b2v[nt][0]  = b2s[col];    b2v[nt][1]  = b2s[col+1];
        cb1v[nt][0] = cb1s[col];   cb1v[nt][1] = cb1s[col+1];
        cw2v[nt][0] = cw2s[col];   cw2v[nt][1] = cw2s[col+1];
    }

    const u32 m1hi_s = cvta_s(m1hi);
    const u32 m1lo_s = cvta_s(m1lo);
    const u32 mbuf_s = cvta_s(mbuf);
    const u32 w2h_s  = cvta_s(smc + SM_W2H);
    const u32 c1h_s  = cvta_s(smc + SM_C1H);
    u32 aoffA[2];
    #pragma unroll
    for (int fr = 0; fr < 2; fr++)
        aoffA[fr] = (u32)((r0 + 16*fr + (l & 15))*LDAB + (l >> 4)*16);
    u32 boffB[2];
    #pragma unroll
    for (int ng = 0; ng < 2; ng++)
        boffB[ng] = (u32)((l & 15)*LDAB + (c0 + 16*ng)*2 + (l >> 4)*16);

    // build-phase constants (this thread's edge row + k-slice)
    const int be  = r0 + (lt >> 2);
    const int bk0 = (lt & 3) * 32;
    const int bii = be >> 4, bjj = be & 15;
    const float* Bmn  = Bms + bii*129 + bk0;
    const float* w1cn = w1c + bk0;
    const float cix = ci[bii*3+0], ciy = ci[bii*3+1], ciz = ci[bii*3+2];
    const float miv = mi[bii];

    const int t_il = lt / 3, t_d = lt - t_il*3;
    float trs_reg = 0.f;

    float aggp[2][4][2];
    #pragma unroll
    for (int fr = 0; fr < 2; fr++)
        #pragma unroll
        for (int nt = 0; nt < 4; nt++) { aggp[fr][nt][0] = 0.f; aggp[fr][nt][1] = 0.f; }

    // ---- prologue: build tile 0 fully ----
    {
        const int jn = b*Nn + bjj;
        const float mkj = mask[jn];
        float m2 = miv*mkj;
        float dx = cix - coord[jn*3+0]*mkj;
        float dy = ciy - coord[jn*3+1]*mkj;
        float dz = ciz - coord[jn*3+2]*mkj;
        float rv = (dx*dx + dy*dy + dz*dz)*m2;
        if ((lt & 3) == 0) m2d[be] = m2;
        const float* gAn = g_A + jn*Ff + bk0;
        #pragma unroll
        for (int c = 0; c < 8; c++) {
            float4 av = *(const float4*)(gAn + c*4);
            float x0 = silu_f(av.x + Bmn[c*4+0] + rv*w1cn[c*4+0]);
            float x1 = silu_f(av.y + Bmn[c*4+1] + rv*w1cn[c*4+1]);
            float x2 = silu_f(av.z + Bmn[c*4+2] + rv*w1cn[c*4+2]);
            float x3 = silu_f(av.w + Bmn[c*4+3] + rv*w1cn[c*4+3]);
            __half h0 = __float2half_rn(x0), h1 = __float2half_rn(x1);
            __half h2 = __float2half_rn(x2), h3 = __float2half_rn(x3);
            uint2 vh, vl;
            vh.x = (*(unsigned short*)&h0) | ((u32)(*(unsigned short*)&h1) << 16);
            vh.y = (*(unsigned short*)&h2) | ((u32)(*(unsigned short*)&h3) << 16);
            vl.x = pkh(x0-__half2float(h0), x1-__half2float(h1));
            vl.y = pkh(x2-__half2float(h2), x3-__half2float(h3));
            int eo = be*LDA + bk0 + c*4;
            *(uint2*)(m1hi + eo) = vh;
            *(uint2*)(m1lo + eo) = vl;
        }
    }
    __syncthreads();

    for (int jt = 0; jt < Nn/16; jt++) {
        // ---- GEMM2: acc = m1 @ W2 (2-term fp16: A hi/lo, W single) ----
        float acc[2][4][4];
        #pragma unroll
        for (int fr = 0; fr < 2; fr++)
            #pragma unroll
            for (int nt = 0; nt < 4; nt++)
                #pragma unroll
                for (int q = 0; q < 4; q++) acc[fr][nt][q] = 0.f;
        #pragma unroll
        for (int k0 = 0; k0 < 8; k0++) {
            u32 ah[2][4], al[2][4], bh[4][2];
            #pragma unroll
            for (int fr = 0; fr < 2; fr++) {
                ldsm4(ah[fr][0], ah[fr][1], ah[fr][2], ah[fr][3], m1hi_s + aoffA[fr] + k0*32);
                ldsm4(al[fr][0], al[fr][1], al[fr][2], al[fr][3], m1lo_s + aoffA[fr] + k0*32);
            }
            #pragma unroll
            for (int ng = 0; ng < 2; ng++)
                ldsm4t(bh[2*ng][0], bh[2*ng][1], bh[2*ng+1][0], bh[2*ng+1][1],
                       w2h_s + boffB[ng] + k0*16*LDAB);
            #pragma unroll
            for (int fr = 0; fr < 2; fr++)
                #pragma unroll
                for (int nt = 0; nt < 4; nt++) {
                    mma_h(acc[fr][nt], ah[fr], bh[nt]);
                    mma_h(acc[fr][nt], al[fr], bh[nt]);
                }
        }

        // ---- prefetch build(t+1) inputs (latency covered by epi2) ----
        const bool do_build = (jt + 1 < Nn/16);
        const int jn1 = b*Nn + (do_build ? (jt+1)*16 : 0) + bjj;
        const float mkj1 = mask[jn1];
        const float cjx1 = coord[jn1*3+0], cjy1 = coord[jn1*3+1], cjz1 = coord[jn1*3+2];
        const float* gA1 = g_A + jn1*Ff + bk0;
        float4 pa[4];
        pa[0] = *(const float4*)(gA1 + 0);
        pa[1] = *(const float4*)(gA1 + 4);
        pa[2] = *(const float4*)(gA1 + 8);
        pa[3] = *(const float4*)(gA1 + 12);

        // ---- epilogue 2 (registers) ----
        const float* m2dc = m2d + (jt & 1)*128;
        #pragma unroll
        for (int fr = 0; fr < 2; fr++) {
            const int rlo = r0 + 16*fr + g;
            const int rhi = rlo + 8;
            const float m2lo = m2dc[rlo];
            const float m2hi = m2dc[rhi];
            #pragma unroll
            for (int nt = 0; nt < 4; nt++) {
                int col = c0 + 8*nt + 2*tg;
                float v0 = silu_f(acc[fr][nt][0] + b2v[nt][0]) * m2lo;
                float v1 = silu_f(acc[fr][nt][1] + b2v[nt][1]) * m2lo;
                float v2 = silu_f(acc[fr][nt][2] + b2v[nt][0]) * m2hi;
                float v3 = silu_f(acc[fr][nt][3] + b2v[nt][1]) * m2hi;
                aggp[fr][nt][0] += v0 + v2;
                aggp[fr][nt][1] += v1 + v3;
                *(u32*)(mbuf + rlo*LDA + col) = pkh(v0, v1);
                *(u32*)(mbuf + rhi*LDA + col) = pkh(v2, v3);
            }
        }
        GBAR(barid);   // mbuf ready; m1 dead for this group -> build(t+1) may write

        // ---- build(t+1) setup ----
        float rv1 = 0.f;
        {
            float m2 = miv*mkj1;
            float dx = cix - cjx1*mkj1;
            float dy = ciy - cjy1*mkj1;
            float dz = ciz - cjz1*mkj1;
            rv1 = (dx*dx + dy*dy + dz*dz)*m2;
            if (do_build && (lt & 3) == 0) m2d[((jt+1) & 1)*128 + be] = m2;
        }

        // ---- GEMM3 k-loop with interleaved build(t+1) chunks ----
        float acc3[2][4][4];
        #pragma unroll
        for (int fr = 0; fr < 2; fr++)
            #pragma unroll
            for (int nt = 0; nt < 4; nt++)
                #pragma unroll
                for (int q = 0; q < 4; q++) acc3[fr][nt][q] = 0.f;
        float4 pb[4];
        #pragma unroll
        for (int k0 = 0; k0 < 8; k0++) {
            u32 af[2][4], bc[4][2];
            #pragma unroll
            for (int fr = 0; fr < 2; fr++)
                ldsm4(af[fr][0], af[fr][1], af[fr][2], af[fr][3], mbuf_s + aoffA[fr] + k0*32);
            #pragma unroll
            for (int ng = 0; ng < 2; ng++)
                ldsm4t(bc[2*ng][0], bc[2*ng][1], bc[2*ng+1][0], bc[2*ng+1][1],
                       c1h_s + boffB[ng] + k0*16*LDAB);
            if (k0 < 4)
                pb[k0] = *(const float4*)(gA1 + 16 + k0*4);
            if (do_build) {
                float4 av = (k0 < 4) ? pa[k0] : pb[k0-4];
                float x0 = silu_f(av.x + Bmn[k0*4+0] + rv1*w1cn[k0*4+0]);
                float x1 = silu_f(av.y + Bmn[k0*4+1] + rv1*w1cn[k0*4+1]);
                float x2 = silu_f(av.z + Bmn[k0*4+2] + rv1*w1cn[k0*4+2]);
                float x3 = silu_f(av.w + Bmn[k0*4+3] + rv1*w1cn[k0*4+3]);
                __half h0 = __float2half_rn(x0), h1 = __float2half_rn(x1);
                __half h2 = __float2half_rn(x2), h3 = __float2half_rn(x3);
                uint2 vh, vl;
                vh.x = (*(unsigned short*)&h0) | ((u32)(*(unsigned short*)&h1) << 16);
                vh.y = (*(unsigned short*)&h2) | ((u32)(*(unsigned short*)&h3) << 16);
                vl.x = pkh(x0-__half2float(h0), x1-__half2float(h1));
                vl.y = pkh(x2-__half2float(h2), x3-__half2float(h3));
                int eo = be*LDA + bk0 + k0*4;
                *(uint2*)(m1hi + eo) = vh;
                *(uint2*)(m1lo + eo) = vl;
            }
            #pragma unroll
            for (int fr = 0; fr < 2; fr++)
                #pragma unroll
                for (int nt = 0; nt < 4; nt++)
                    mma_h(acc3[fr][nt], af[fr], bc[nt]);
        }

        // ---- epilogue 3 (registers): embed partials ----
        #pragma unroll
        for (int fr = 0; fr < 2; fr++) {
            float plo = 0.f, phi = 0.f;
            #pragma unroll
            for (int nt = 0; nt < 4; nt++) {
                plo += silu_f(acc3[fr][nt][0] + cb1v[nt][0]) * cw2v[nt][0];
                plo += silu_f(acc3[fr][nt][1] + cb1v[nt][1]) * cw2v[nt][1];
                phi += silu_f(acc3[fr][nt][2] + cb1v[nt][0]) * cw2v[nt][0];
                phi += silu_f(acc3[fr][nt][3] + cb1v[nt][1]) * cw2v[nt][1];
            }
            plo += __shfl_xor_sync(0xffffffffu, plo, 1);
            plo += __shfl_xor_sync(0xffffffffu, plo, 2);
            phi += __shfl_xor_sync(0xffffffffu, phi, 1);
            phi += __shfl_xor_sync(0xffffffffu, phi, 2);
            if (tg == 0) {
                embP[wc*128 + r0 + 16*fr + g]     = plo;
                embP[wc*128 + r0 + 16*fr + g + 8] = phi;
            }
        }
        GBAR(barid);   // embP ready; m1(t+1) fully built for this group

        // ---- trans accumulation (6 threads/group, deterministic) ----
        if (lt < 6) {
            const int ii = 2*wr + t_il;
            const float cid = ci[ii*3 + t_d];
            const int j0 = jt*16;
            float s = 0.f;
            #pragma unroll
            for (int jj = 0; jj < 16; jj++) {
                int e = ii*16 + jj;
                int jn = b*Nn + j0 + jj;
                float m2 = m2dc[e];
                float cjd = coord[jn*3 + t_d]*mask[jn];
                float em = embP[e] + embP[128+e] + embP[256+e] + embP[384+e];
                s += (cid - cjd)*m2*em*m2;
            }
            trs_reg += s;
        }
    }

    // ---- final agg reduction ----
    #pragma unroll
    for (int fr = 0; fr < 2; fr++) {
        #pragma unroll
        for (int nt = 0; nt < 4; nt++) {
            #pragma unroll
            for (int q = 0; q < 2; q++) {
                float v = aggp[fr][nt][q];
                v += __shfl_xor_sync(0xffffffffu, v, 4);
                v += __shfl_xor_sync(0xffffffffu, v, 8);
                v += __shfl_xor_sync(0xffffffffu, v, 16);
                if (l < 4)
                    g_agg[(b*Nn + i0 + 2*wr + fr)*Ff + c0 + 8*nt + 2*tg + q] = v;
            }
        }
    }
    if (lt < 6)
        g_trans[(b*Nn + i0 + 2*wr + t_il)*3 + t_d] = trs_reg;
}

// ---------------------------------------------------------------------------
// k_node: 4 nodes/block, 512 threads; dual accumulators for chain ILP
// ---------------------------------------------------------------------------
__global__ __launch_bounds__(512) void k_node(
    const float* __restrict__ coord, const float* __restrict__ mask,
    const float* __restrict__ nw1, const float* __restrict__ nb1,
    const float* __restrict__ nw2, const float* __restrict__ nb2,
    float* __restrict__ out)
{
    __shared__ float nin[4][2*Ff];
    __shared__ float t1s[4][Ff];
    __shared__ float red[512];
    const int t  = threadIdx.x;
    const int r0 = blockIdx.x * 4;
    const int b  = r0 >> 9;
    const int nd = t >> 7, f = t & 127;
    const int r  = r0 + nd;

    {
        float mk = mask[r];
        nin[nd][f]      = g_hm[r*Ff + f] * mk;
        nin[nd][Ff + f] = g_agg[r*Ff + f] * mk;
    }
    red[t] = mask[b*Nn + t];
    __syncthreads();
    for (int off = 256; off >= 1; off >>= 1) {
        if (t < off) red[t] += red[t + off];
        __syncthreads();
    }

    float a0 = nb1[f], a1 = 0.f;
    #pragma unroll 8
    for (int k = 0; k < 2*Ff; k += 2) {
        a0 += nin[nd][k]*nw1[k*Ff + f];
        a1 += nin[nd][k+1]*nw1[(k+1)*Ff + f];
    }
    t1s[nd][f] = silu_f(a0 + a1);
    __syncthreads();
    float c0 = nb2[f], c1 = 0.f;
    #pragma unroll 8
    for (int k = 0; k < Ff; k += 2) {
        c0 += t1s[nd][k]*nw2[k*Ff + f];
        c1 += t1s[nd][k+1]*nw2[(k+1)*Ff + f];
    }
    {
        float mk = mask[r];
        out[r*Ff + f] = (g_hm[r*Ff + f] + c0 + c1)*mk;
    }
    if (t < 12) {
        int nd2 = t/3, d = t - nd2*3;
        int rr = r0 + nd2;
        float mk = mask[rr];
        float denom = mk*red[0] + 1e-10f;
        float cm = coord[rr*3 + d]*mk;
        out[Bb*Nn*Ff + rr*3 + d] = (cm + g_trans[rr*3 + d]/denom)*mk;
    }
}

// ---------------------------------------------------------------------------
extern "C" void kernel_launch(void* const* d_in, const int* in_sizes, int n_in,
                              void* d_out, int out_size)
{
    const float* h     = (const float*)d_in[0];
    const float* coord = (const float*)d_in[1];
    const float* mask  = (const float*)d_in[2];
    const float* ew1   = (const float*)d_in[3];
    const float* eb1   = (const float*)d_in[4];
    const float* ew2   = (const float*)d_in[5];
    const float* eb2   = (const float*)d_in[6];
    const float* nw1   = (const float*)d_in[7];
    const float* nb1   = (const float*)d_in[8];
    const float* nw2   = (const float*)d_in[9];
    const float* nb2   = (const float*)d_in[10];
    const float* cw1   = (const float*)d_in[11];
    const float* cb1   = (const float*)d_in[12];
    const float* cw2   = (const float*)d_in[13];

    cudaFuncSetAttribute(k_edge, cudaFuncAttributeMaxDynamicSharedMemorySize, SM_TOTAL);

    k_prep<<<Bb*Nn/4, 512>>>(h, mask, ew1, eb1, ew2, cw1);
    k_edge<<<Bb*(Nn/8), 512, SM_TOTAL>>>(coord, mask, ew1, eb2, cb1, cw2);
    k_node<<<Bb*Nn/4, 512>>>(coord, mask, nw1, nb1, nw2, nb2, (float*)d_out);
}

// round 16
// speedup vs baseline: 1.4331x; 1.2040x over previous
#include <cuda_runtime.h>
#include <cuda_fp16.h>

#define Bb 2
#define Nn 512
#define Ff 128
#define LDA 136          /* elements per fp16 tile row (272B) */
#define LDAB 272
#define ROWU4 17

typedef unsigned int u32;
typedef unsigned long long u64;

// ------------------------- device scratch (no allocs) -------------------------
__device__ float g_A[Bb*Nn*Ff];
__device__ float g_Bm[Bb*Nn*Ff];
__device__ float g_hm[Bb*Nn*Ff];
__device__ float g_agg[Bb*Nn*Ff];
__device__ float g_trans[Bb*Nn*3];
__device__ __half g_w2h[Ff*Ff];   // W2 fp16, [k][f]
__device__ __half g_c1h[Ff*Ff];   // coord_w1 fp16, [k][f]

// silu via single-MUFU tanh: silu(x) = 0.5x*(1+tanh(0.5x))
__device__ __forceinline__ float silu_f(float x) {
    float xh = 0.5f*x, t;
    asm("tanh.approx.f32 %0, %1;" : "=f"(t) : "f"(xh));
    return xh + xh*t;
}
__device__ __forceinline__ u32 pkh(float a, float b) {
    __half2 t = __floats2half2_rn(a, b);
    return *(u32*)&t;
}
__device__ __forceinline__ u32 cvta_s(const void* p) {
    u32 a; asm("{ .reg .u64 t; cvta.to.shared.u64 t, %1; cvt.u32.u64 %0, t; }" : "=r"(a) : "l"(p));
    return a;
}
__device__ __forceinline__ void ldsm4(u32 &a0, u32 &a1, u32 &a2, u32 &a3, u32 addr) {
    asm volatile("ldmatrix.sync.aligned.m8n8.x4.shared.b16 {%0,%1,%2,%3}, [%4];"
                 : "=r"(a0), "=r"(a1), "=r"(a2), "=r"(a3) : "r"(addr));
}
__device__ __forceinline__ void ldsm4t(u32 &a0, u32 &a1, u32 &a2, u32 &a3, u32 addr) {
    asm volatile("ldmatrix.sync.aligned.m8n8.x4.trans.shared.b16 {%0,%1,%2,%3}, [%4];"
                 : "=r"(a0), "=r"(a1), "=r"(a2), "=r"(a3) : "r"(addr));
}
__device__ __forceinline__ void mma_h(float* c, const u32* a, const u32* b) {
    asm volatile("mma.sync.aligned.m16n8k16.row.col.f32.f16.f16.f32 "
                 "{%0,%1,%2,%3}, {%4,%5,%6,%7}, {%8,%9}, {%0,%1,%2,%3};"
                 : "+f"(c[0]), "+f"(c[1]), "+f"(c[2]), "+f"(c[3])
                 : "r"(a[0]), "r"(a[1]), "r"(a[2]), "r"(a[3]), "r"(b[0]), "r"(b[1]));
}
#define GBAR(id) asm volatile("bar.sync %0, 128;" :: "r"(id) : "memory")

// ------------------------- SMEM layout (bytes) -------------------------
#define SM_M1   0                            /* 128*272 = 34816 */
#define SM_MBUF (SM_M1 + 34816)
#define SM_W2H  (SM_MBUF + 34816)
#define SM_C1H  (SM_W2H + 34816)
#define SM_BMS  (SM_C1H + 34816)             /* 8*129*4 = 4128 */
#define SM_W1C  (SM_BMS + 4128)
#define SM_B2S  (SM_W1C + 512)
#define SM_CB1S (SM_B2S + 512)
#define SM_CW2S (SM_CB1S + 512)
#define SM_M2D  (SM_CW2S + 512)              /* double-buffered 2*128*4 */
#define SM_EMBP (SM_M2D + 1024)              /* 4*128*4 = 2048 */
#define SM_CI   (SM_EMBP + 2048)
#define SM_MI   (SM_CI + 96)
#define SM_TOTAL (SM_MI + 32 + 16)

// ---------------------------------------------------------------------------
// k_prep: 4 nodes/block, 512 threads; fused fp16 weight conversion; grid = 256
// ---------------------------------------------------------------------------
__global__ __launch_bounds__(512) void k_prep(
    const float* __restrict__ h, const float* __restrict__ mask,
    const float* __restrict__ ew1, const float* __restrict__ eb1,
    const float* __restrict__ ew2, const float* __restrict__ cw1)
{
    __shared__ float hr[4][Ff];
    const int t  = threadIdx.x;
    const int r0 = blockIdx.x * 4;
    const int nd = t >> 7, f = t & 127;
    {
        float hv = h[(r0+nd)*Ff + f] * mask[r0+nd];
        hr[nd][f] = hv;
        g_hm[(r0+nd)*Ff + f] = hv;
    }
    // fused fp16 weight conversion (independent work)
    {
        int widx = blockIdx.x*512 + t;
        if (widx < 2*Ff*Ff) {
            int mat = widx >> 14, rem = widx & 16383;
            if (mat == 0) g_w2h[rem] = __float2half_rn(ew2[rem]);
            else          g_c1h[rem] = __float2half_rn(cw1[rem]);
        }
    }
    __syncthreads();
    float a0 = 0.f, a1 = 0.f;
    float b0 = eb1[f], b1 = 0.f;
    #pragma unroll 8
    for (int k = 0; k < Ff; k += 2) {
        float h0 = hr[nd][k], h1 = hr[nd][k+1];
        a0 += h0 * ew1[k*Ff + f];
        a1 += h1 * ew1[(k+1)*Ff + f];
        b0 += h0 * ew1[(Ff + k)*Ff + f];
        b1 += h1 * ew1[(Ff + k + 1)*Ff + f];
    }
    g_A[(r0+nd)*Ff + f]  = a0 + a1;
    g_Bm[(r0+nd)*Ff + f] = b0 + b1;
}

// ---------------------------------------------------------------------------
// k_edge: 128 blocks, 512 threads; 4 row-groups; build(t+1) overlapped
// into GEMM3(t); single-term fp16 GEMMs (no hi/lo split).
// ---------------------------------------------------------------------------
__global__ __launch_bounds__(512, 1) void k_edge(
    const float* __restrict__ coord, const float* __restrict__ mask,
    const float* __restrict__ ew1,   const float* __restrict__ eb2,
    const float* __restrict__ cb1,   const float* __restrict__ cw2)
{
    extern __shared__ char smc[];
    __half* m1   = (__half*)(smc + SM_M1);
    __half* mbuf = (__half*)(smc + SM_MBUF);
    float* Bms  = (float*)(smc + SM_BMS);
    float* w1c  = (float*)(smc + SM_W1C);
    float* b2s  = (float*)(smc + SM_B2S);
    float* cb1s = (float*)(smc + SM_CB1S);
    float* cw2s = (float*)(smc + SM_CW2S);
    float* m2d  = (float*)(smc + SM_M2D);    /* [2][128] */
    float* embP = (float*)(smc + SM_EMBP);
    float* ci   = (float*)(smc + SM_CI);
    float* mi   = (float*)(smc + SM_MI);

    const int tid = threadIdx.x;
    const int l   = tid & 31;
    const int wr  = tid >> 7;            // row-group 0..3
    const int wc  = (tid >> 5) & 3;      // column warp within group
    const int lt  = tid & 127;
    const int r0  = wr * 32, c0 = wc * 32;
    const int g   = l >> 2, tg = l & 3;
    const int b   = blockIdx.x >> 6;
    const int i0  = (blockIdx.x & 63) * 8;
    const int barid = wr + 1;

    // --- prologue: stage weights + per-block constants ---
    {
        uint4* s1 = (uint4*)(smc + SM_W2H);
        uint4* s3 = (uint4*)(smc + SM_C1H);
        const uint4* d1 = (const uint4*)g_w2h;
        const uint4* d3 = (const uint4*)g_c1h;
        for (int idx = tid; idx < 128*16; idx += 512) {
            int k = idx >> 4, u = idx & 15;
            s1[k*ROWU4 + u] = d1[idx];
            s3[k*ROWU4 + u] = d3[idx];
        }
    }
    if (tid < Ff) {
        w1c[tid]  = ew1[2*Ff*Ff + tid];
        b2s[tid]  = eb2[tid];
        cb1s[tid] = cb1[tid];
        cw2s[tid] = cw2[tid];
    }
    if (tid < 8) {
        float mk = mask[b*Nn + i0 + tid];
        mi[tid] = mk;
        ci[tid*3+0] = coord[(b*Nn+i0+tid)*3+0]*mk;
        ci[tid*3+1] = coord[(b*Nn+i0+tid)*3+1]*mk;
        ci[tid*3+2] = coord[(b*Nn+i0+tid)*3+2]*mk;
    }
    for (int idx = tid; idx < 8*Ff; idx += 512) {
        int ii = idx >> 7, f = idx & 127;
        Bms[ii*129 + f] = g_Bm[(b*Nn + i0 + ii)*Ff + f];
    }
    __syncthreads();

    // --- per-thread hoisted epilogue constants ---
    float b2v[4][2], cb1v[4][2], cw2v[4][2];
    #pragma unroll
    for (int nt = 0; nt < 4; nt++) {
        int col = c0 + 8*nt + 2*tg;
        b2v[nt][0]  = b2s[col];    b2v[nt][1]  = b2s[col+1];
        cb1v[nt][0] = cb1s[col];   cb1v[nt][1] = cb1s[col+1];
        cw2v[nt][0] = cw2s[col];   cw2v[nt][1] = cw2s[col+1];
    }

    const u32 m1_s   = cvta_s(m1);
    const u32 mbuf_s = cvta_s(mbuf);
    const u32 w2h_s  = cvta_s(smc + SM_W2H);
    const u32 c1h_s  = cvta_s(smc + SM_C1H);
    u32 aoffA[2];
    #pragma unroll
    for (int fr = 0; fr < 2; fr++)
        aoffA[fr] = (u32)((r0 + 16*fr + (l & 15))*LDAB + (l >> 4)*16);
    u32 boffB[2];
    #pragma unroll
    for (int ng = 0; ng < 2; ng++)
        boffB[ng] = (u32)((l & 15)*LDAB + (c0 + 16*ng)*2 + (l >> 4)*16);

    // build-phase constants (this thread's edge row + k-slice)
    const int be  = r0 + (lt >> 2);
    const int bk0 = (lt & 3) * 32;
    const int bii = be >> 4, bjj = be & 15;
    const float* Bmn  = Bms + bii*129 + bk0;
    const float* w1cn = w1c + bk0;
    const float cix = ci[bii*3+0], ciy = ci[bii*3+1], ciz = ci[bii*3+2];
    const float miv = mi[bii];

    const int t_il = lt / 3, t_d = lt - t_il*3;
    float trs_reg = 0.f;

    float aggp[2][4][2];
    #pragma unroll
    for (int fr = 0; fr < 2; fr++)
        #pragma unroll
        for (int nt = 0; nt < 4; nt++) { aggp[fr][nt][0] = 0.f; aggp[fr][nt][1] = 0.f; }

    // ---- prologue: build tile 0 fully ----
    {
        const int jn = b*Nn + bjj;
        const float mkj = mask[jn];
        float m2 = miv*mkj;
        float dx = cix - coord[jn*3+0]*mkj;
        float dy = ciy - coord[jn*3+1]*mkj;
        float dz = ciz - coord[jn*3+2]*mkj;
        float rv = (dx*dx + dy*dy + dz*dz)*m2;
        if ((lt & 3) == 0) m2d[be] = m2;
        const float* gAn = g_A + jn*Ff + bk0;
        #pragma unroll
        for (int c = 0; c < 4; c++) {
            float4 av  = *(const float4*)(gAn + c*8);
            float4 av2 = *(const float4*)(gAn + c*8 + 4);
            float x0 = silu_f(av.x  + Bmn[c*8+0] + rv*w1cn[c*8+0]);
            float x1 = silu_f(av.y  + Bmn[c*8+1] + rv*w1cn[c*8+1]);
            float x2 = silu_f(av.z  + Bmn[c*8+2] + rv*w1cn[c*8+2]);
            float x3 = silu_f(av.w  + Bmn[c*8+3] + rv*w1cn[c*8+3]);
            float x4 = silu_f(av2.x + Bmn[c*8+4] + rv*w1cn[c*8+4]);
            float x5 = silu_f(av2.y + Bmn[c*8+5] + rv*w1cn[c*8+5]);
            float x6 = silu_f(av2.z + Bmn[c*8+6] + rv*w1cn[c*8+6]);
            float x7 = silu_f(av2.w + Bmn[c*8+7] + rv*w1cn[c*8+7]);
            uint4 vh;
            vh.x = pkh(x0, x1); vh.y = pkh(x2, x3);
            vh.z = pkh(x4, x5); vh.w = pkh(x6, x7);
            *(uint4*)(m1 + be*LDA + bk0 + c*8) = vh;
        }
    }
    __syncthreads();

    for (int jt = 0; jt < Nn/16; jt++) {
        // ---- GEMM2: acc = m1 @ W2 (single fp16 term) ----
        float acc[2][4][4];
        #pragma unroll
        for (int fr = 0; fr < 2; fr++)
            #pragma unroll
            for (int nt = 0; nt < 4; nt++)
                #pragma unroll
                for (int q = 0; q < 4; q++) acc[fr][nt][q] = 0.f;
        #pragma unroll
        for (int k0 = 0; k0 < 8; k0++) {
            u32 ah[2][4], bh[4][2];
            #pragma unroll
            for (int fr = 0; fr < 2; fr++)
                ldsm4(ah[fr][0], ah[fr][1], ah[fr][2], ah[fr][3], m1_s + aoffA[fr] + k0*32);
            #pragma unroll
            for (int ng = 0; ng < 2; ng++)
                ldsm4t(bh[2*ng][0], bh[2*ng][1], bh[2*ng+1][0], bh[2*ng+1][1],
                       w2h_s + boffB[ng] + k0*16*LDAB);
            #pragma unroll
            for (int fr = 0; fr < 2; fr++)
                #pragma unroll
                for (int nt = 0; nt < 4; nt++)
                    mma_h(acc[fr][nt], ah[fr], bh[nt]);
        }

        // ---- prefetch build(t+1) inputs (latency covered by epi2) ----
        const bool do_build = (jt + 1 < Nn/16);
        const int jn1 = b*Nn + (do_build ? (jt+1)*16 : 0) + bjj;
        const float mkj1 = mask[jn1];
        const float cjx1 = coord[jn1*3+0], cjy1 = coord[jn1*3+1], cjz1 = coord[jn1*3+2];
        const float* gA1 = g_A + jn1*Ff + bk0;
        float4 pa[4];
        pa[0] = *(const float4*)(gA1 + 0);
        pa[1] = *(const float4*)(gA1 + 4);
        pa[2] = *(const float4*)(gA1 + 8);
        pa[3] = *(const float4*)(gA1 + 12);

        // ---- epilogue 2 (registers) ----
        const float* m2dc = m2d + (jt & 1)*128;
        #pragma unroll
        for (int fr = 0; fr < 2; fr++) {
            const int rlo = r0 + 16*fr + g;
            const int rhi = rlo + 8;
            const float m2lo = m2dc[rlo];
            const float m2hi = m2dc[rhi];
            #pragma unroll
            for (int nt = 0; nt < 4; nt++) {
                int col = c0 + 8*nt + 2*tg;
                float v0 = silu_f(acc[fr][nt][0] + b2v[nt][0]) * m2lo;
                float v1 = silu_f(acc[fr][nt][1] + b2v[nt][1]) * m2lo;
                float v2 = silu_f(acc[fr][nt][2] + b2v[nt][0]) * m2hi;
                float v3 = silu_f(acc[fr][nt][3] + b2v[nt][1]) * m2hi;
                aggp[fr][nt][0] += v0 + v2;
                aggp[fr][nt][1] += v1 + v3;
                *(u32*)(mbuf + rlo*LDA + col) = pkh(v0, v1);
                *(u32*)(mbuf + rhi*LDA + col) = pkh(v2, v3);
            }
        }
        GBAR(barid);   // mbuf ready; m1 dead for this group -> build(t+1) may write

        // ---- build(t+1) setup ----
        float rv1 = 0.f;
        {
            float m2 = miv*mkj1;
            float dx = cix - cjx1*mkj1;
            float dy = ciy - cjy1*mkj1;
            float dz = ciz - cjz1*mkj1;
            rv1 = (dx*dx + dy*dy + dz*dz)*m2;
            if (do_build && (lt & 3) == 0) m2d[((jt+1) & 1)*128 + be] = m2;
        }

        // ---- GEMM3 k-loop with interleaved build(t+1) chunks ----
        float acc3[2][4][4];
        #pragma unroll
        for (int fr = 0; fr < 2; fr++)
            #pragma unroll
            for (int nt = 0; nt < 4; nt++)
                #pragma unroll
                for (int q = 0; q < 4; q++) acc3[fr][nt][q] = 0.f;
        float4 pb[4];
        #pragma unroll
        for (int k0 = 0; k0 < 8; k0++) {
            u32 af[2][4], bc[4][2];
            #pragma unroll
            for (int fr = 0; fr < 2; fr++)
                ldsm4(af[fr][0], af[fr][1], af[fr][2], af[fr][3], mbuf_s + aoffA[fr] + k0*32);
            #pragma unroll
            for (int ng = 0; ng < 2; ng++)
                ldsm4t(bc[2*ng][0], bc[2*ng][1], bc[2*ng+1][0], bc[2*ng+1][1],
                       c1h_s + boffB[ng] + k0*16*LDAB);
            if (k0 < 4)
                pb[k0] = *(const float4*)(gA1 + 16 + k0*4);
            if (do_build) {
                float4 av = (k0 < 4) ? pa[k0] : pb[k0-4];
                float x0 = silu_f(av.x + Bmn[k0*4+0] + rv1*w1cn[k0*4+0]);
                float x1 = silu_f(av.y + Bmn[k0*4+1] + rv1*w1cn[k0*4+1]);
                float x2 = silu_f(av.z + Bmn[k0*4+2] + rv1*w1cn[k0*4+2]);
                float x3 = silu_f(av.w + Bmn[k0*4+3] + rv1*w1cn[k0*4+3]);
                uint2 vh;
                vh.x = pkh(x0, x1);
                vh.y = pkh(x2, x3);
                *(uint2*)(m1 + be*LDA + bk0 + k0*4) = vh;
            }
            #pragma unroll
            for (int fr = 0; fr < 2; fr++)
                #pragma unroll
                for (int nt = 0; nt < 4; nt++)
                    mma_h(acc3[fr][nt], af[fr], bc[nt]);
        }

        // ---- epilogue 3 (registers): embed partials ----
        #pragma unroll
        for (int fr = 0; fr < 2; fr++) {
            float plo = 0.f, phi = 0.f;
            #pragma unroll
            for (int nt = 0; nt < 4; nt++) {
                plo += silu_f(acc3[fr][nt][0] + cb1v[nt][0]) * cw2v[nt][0];
                plo += silu_f(acc3[fr][nt][1] + cb1v[nt][1]) * cw2v[nt][1];
                phi += silu_f(acc3[fr][nt][2] + cb1v[nt][0]) * cw2v[nt][0];
                phi += silu_f(acc3[fr][nt][3] + cb1v[nt][1]) * cw2v[nt][1];
            }
            plo += __shfl_xor_sync(0xffffffffu, plo, 1);
            plo += __shfl_xor_sync(0xffffffffu, plo, 2);
            phi += __shfl_xor_sync(0xffffffffu, phi, 1);
            phi += __shfl_xor_sync(0xffffffffu, phi, 2);
            if (tg == 0) {
                embP[wc*128 + r0 + 16*fr + g]     = plo;
                embP[wc*128 + r0 + 16*fr + g + 8] = phi;
            }
        }
        GBAR(barid);   // embP ready; m1(t+1) fully built for this group

        // ---- trans accumulation (6 threads/group, deterministic) ----
        if (lt < 6) {
            const int ii = 2*wr + t_il;
            const float cid = ci[ii*3 + t_d];
            const int j0 = jt*16;
            float s = 0.f;
            #pragma unroll
            for (int jj = 0; jj < 16; jj++) {
                int e = ii*16 + jj;
                int jn = b*Nn + j0 + jj;
                float m2 = m2dc[e];
                float cjd = coord[jn*3 + t_d]*mask[jn];
                float em = embP[e] + embP[128+e] + embP[256+e] + embP[384+e];
                s += (cid - cjd)*m2*em*m2;
            }
            trs_reg += s;
        }
    }

    // ---- final agg reduction ----
    #pragma unroll
    for (int fr = 0; fr < 2; fr++) {
        #pragma unroll
        for (int nt = 0; nt < 4; nt++) {
            #pragma unroll
            for (int q = 0; q < 2; q++) {
                float v = aggp[fr][nt][q];
                v += __shfl_xor_sync(0xffffffffu, v, 4);
                v += __shfl_xor_sync(0xffffffffu, v, 8);
                v += __shfl_xor_sync(0xffffffffu, v, 16);
                if (l < 4)
                    g_agg[(b*Nn + i0 + 2*wr + fr)*Ff + c0 + 8*nt + 2*tg + q] = v;
            }
        }
    }
    if (lt < 6)
        g_trans[(b*Nn + i0 + 2*wr + t_il)*3 + t_d] = trs_reg;
}

// ---------------------------------------------------------------------------
// k_node: 4 nodes/block, 512 threads; dual accumulators for chain ILP
// ---------------------------------------------------------------------------
__global__ __launch_bounds__(512) void k_node(
    const float* __restrict__ coord, const float* __restrict__ mask,
    const float* __restrict__ nw1, const float* __restrict__ nb1,
    const float* __restrict__ nw2, const float* __restrict__ nb2,
    float* __restrict__ out)
{
    __shared__ float nin[4][2*Ff];
    __shared__ float t1s[4][Ff];
    __shared__ float red[512];
    const int t  = threadIdx.x;
    const int r0 = blockIdx.x * 4;
    const int b  = r0 >> 9;
    const int nd = t >> 7, f = t & 127;
    const int r  = r0 + nd;

    {
        float mk = mask[r];
        nin[nd][f]      = g_hm[r*Ff + f] * mk;
        nin[nd][Ff + f] = g_agg[r*Ff + f] * mk;
    }
    red[t] = mask[b*Nn + t];
    __syncthreads();
    for (int off = 256; off >= 1; off >>= 1) {
        if (t < off) red[t] += red[t + off];
        __syncthreads();
    }

    float a0 = nb1[f], a1 = 0.f;
    #pragma unroll 8
    for (int k = 0; k < 2*Ff; k += 2) {
        a0 += nin[nd][k]*nw1[k*Ff + f];
        a1 += nin[nd][k+1]*nw1[(k+1)*Ff + f];
    }
    t1s[nd][f] = silu_f(a0 + a1);
    __syncthreads();
    float c0 = nb2[f], c1 = 0.f;
    #pragma unroll 8
    for (int k = 0; k < Ff; k += 2) {
        c0 += t1s[nd][k]*nw2[k*Ff + f];
        c1 += t1s[nd][k+1]*nw2[(k+1)*Ff + f];
    }
    {
        float mk = mask[r];
        out[r*Ff + f] = (g_hm[r*Ff + f] + c0 + c1)*mk;
    }
    if (t < 12) {
        int nd2 = t/3, d = t - nd2*3;
        int rr = r0 + nd2;
        float mk = mask[rr];
        float denom = mk*red[0] + 1e-10f;
        float cm = coord[rr*3 + d]*mk;
        out[Bb*Nn*Ff + rr*3 + d] = (cm + g_trans[rr*3 + d]/denom)*mk;
    }
}

// ---------------------------------------------------------------------------
extern "C" void kernel_launch(void* const* d_in, const int* in_sizes, int n_in,
                              void* d_out, int out_size)
{
    const float* h     = (const float*)d_in[0];
    const float* coord = (const float*)d_in[1];
    const float* mask  = (const float*)d_in[2];
    const float* ew1   = (const float*)d_in[3];
    const float* eb1   = (const float*)d_in[4];
    const float* ew2   = (const float*)d_in[5];
    const float* eb2   = (const float*)d_in[6];
    const float* nw1   = (const float*)d_in[7];
    const float* nb1   = (const float*)d_in[8];
    const float* nw2   = (const float*)d_in[9];
    const float* nb2   = (const float*)d_in[10];
    const float* cw1   = (const float*)d_in[11];
    const float* cb1   = (const float*)d_in[12];
    const float* cw2   = (const float*)d_in[13];

    cudaFuncSetAttribute(k_edge, cudaFuncAttributeMaxDynamicSharedMemorySize, SM_TOTAL);

    k_prep<<<Bb*Nn/4, 512>>>(h, mask, ew1, eb1, ew2, cw1);
    k_edge<<<Bb*(Nn/8), 512, SM_TOTAL>>>(coord, mask, ew1, eb2, cb1, cw2);
    k_node<<<Bb*Nn/4, 512>>>(coord, mask, nw1, nb1, nw2, nb2, (float*)d_out);
}